// round 4
// baseline (speedup 1.0000x reference)
#include <cuda_runtime.h>
#include <math.h>

// Problem constants
#define NB    8192
#define TT    48
#define HH    256
#define NENV  10
#define NIN   16
#define FOURH 1024

// GEMM tile config: 128x128 block, 128 threads, 8x16 per thread, KB=8, 3-stage
#define BM     128
#define BN     128
#define KB     8
#define STAGES 3
#define NTHR   128

// ---------------------------------------------------------------------------
// Scratch (static device globals)
// ---------------------------------------------------------------------------
__device__ float g_hT[2][2][HH * NB];        // [layer][pingpong][h][n]  (transposed!)
__device__ float g_cT[2][HH * NB];           // [layer][h][n]
__device__ float g_featsT[TT * NIN * NB];    // [t][f][n]
__device__ float g_Whh_t[2][HH * FOURH];     // [layer][k*1024 + s], s = h*4+gate
__device__ float g_Wih1_t[HH * FOURH];
__device__ float g_Wc_t[NIN * FOURH];        // folded W_ih0 @ W_in
__device__ float g_bias[2][FOURH];

__device__ __forceinline__ float sigm(float v) {
    return 1.0f / (1.0f + __expf(-v));
}
__device__ __forceinline__ float tanh_fast(float v) {
    return 2.0f / (1.0f + __expf(-2.0f * v)) - 1.0f;
}

// ---------------------------------------------------------------------------
// Prep kernels
// ---------------------------------------------------------------------------
__global__ void zero_kernel() {
    const size_t tot = (size_t)HH * NB;
    for (size_t i = (size_t)blockIdx.x * blockDim.x + threadIdx.x; i < tot;
         i += (size_t)gridDim.x * blockDim.x) {
        g_hT[0][0][i] = 0.0f;
        g_hT[1][0][i] = 0.0f;
        g_cT[0][i] = 0.0f;
        g_cT[1][i] = 0.0f;
    }
}

// featsT[t][f][n]
__global__ void prep_feats(const float* __restrict__ x,
                           const float* __restrict__ coords,
                           const float* __restrict__ env,
                           const float* __restrict__ areas,
                           const float* __restrict__ bird_uv) {
    const int tot = TT * NIN * NB;
    for (int idx = blockIdx.x * blockDim.x + threadIdx.x; idx < tot;
         idx += gridDim.x * blockDim.x) {
        int n = idx & (NB - 1);
        int f = (idx >> 13) & 15;
        int t = idx >> 17;
        float v;
        if (f == 0)       v = x[(size_t)n * TT + t];
        else if (f <= 2)  v = coords[n * 2 + (f - 1)];
        else if (f <= 12) v = env[((size_t)n * NENV + (f - 3)) * TT + t];
        else if (f == 13) v = areas[n];
        else              v = bird_uv[((size_t)n * 2 + (f - 14)) * TT + t];
        g_featsT[idx] = v;
    }
}

// Transpose+permute weights to [k][s] layout, s = h*4+gate (i,f,g,o)
__global__ void prep_transpose(const float* __restrict__ W_ih,
                               const float* __restrict__ W_hh,
                               const float* __restrict__ b_ih,
                               const float* __restrict__ b_hh) {
    const int tot = 262144 * 3 + 2048;
    for (int i = blockIdx.x * blockDim.x + threadIdx.x; i < tot;
         i += gridDim.x * blockDim.x) {
        if (i < 524288) {
            int l = i >> 18;
            int r = i & 262143;
            int k = r >> 10;
            int s = r & 1023;
            int g = s & 3;
            int h = s >> 2;
            g_Whh_t[l][r] = W_hh[l * 262144 + (g * HH + h) * HH + k];
        } else if (i < 786432) {
            int r = i - 524288;
            int k = r >> 10;
            int s = r & 1023;
            int g = s & 3;
            int h = s >> 2;
            g_Wih1_t[r] = W_ih[262144 + (g * HH + h) * HH + k];
        } else {
            int j = i - 786432;
            int l = j >> 10;
            int s = j & 1023;
            int g = s & 3;
            int h = s >> 2;
            int row = l * FOURH + g * HH + h;
            g_bias[l][s] = b_ih[row] + b_hh[row];
        }
    }
}

__global__ void prep_wc(const float* __restrict__ W_in,
                        const float* __restrict__ W_ih) {
    int i = blockIdx.x * blockDim.x + threadIdx.x;
    if (i >= NIN * FOURH) return;
    int f = i & 15;
    int s = i >> 4;
    int g = s & 3;
    int h = s >> 2;
    const float* wr = W_ih + (g * HH + h) * HH;
    float acc = 0.0f;
    #pragma unroll 8
    for (int k = 0; k < HH; k++)
        acc = fmaf(wr[k], W_in[k * NIN + f], acc);
    g_Wc_t[f * FOURH + s] = acc;
}

// ---------------------------------------------------------------------------
// Fused LSTM step. 128 threads, 128x128 output tile, 8x16 per thread.
// All operands are [k][*]-contiguous -> cp.async 3-stage pipeline.
// ---------------------------------------------------------------------------
__device__ __forceinline__ void issue_tile(const float* __restrict__ A0,
                                           const float* __restrict__ B0,
                                           const float* __restrict__ A1,
                                           const float* __restrict__ B1,
                                           int K0TILES, int j, int st,
                                           float (*As)[KB][BM],
                                           float (*Bs)[KB][BN],
                                           int rowbase, int sbase,
                                           int kk, int lane) {
    const float* Ab;
    const float* Bb;
    int kl;
    if (j < K0TILES) { Ab = A0; Bb = B0; kl = j; }
    else             { Ab = A1; Bb = B1; kl = j - K0TILES; }
    const float* asrc = Ab + (size_t)(kl * KB + kk) * NB + rowbase + lane * 8;
    const float* bsrc = Bb + (size_t)(kl * KB + kk) * FOURH + sbase + lane * 8;
    unsigned ad = (unsigned)__cvta_generic_to_shared(&As[st][kk][lane * 8]);
    unsigned bd = (unsigned)__cvta_generic_to_shared(&Bs[st][kk][lane * 8]);
    asm volatile(
        "cp.async.cg.shared.global [%0], [%1], 16;\n"
        "cp.async.cg.shared.global [%2], [%3], 16;\n"
        "cp.async.cg.shared.global [%4], [%5], 16;\n"
        "cp.async.cg.shared.global [%6], [%7], 16;\n"
        :: "r"(ad), "l"(asrc), "r"(ad + 16), "l"(asrc + 4),
           "r"(bd), "l"(bsrc), "r"(bd + 16), "l"(bsrc + 4));
    asm volatile("cp.async.commit_group;");
}

template <int LAYER>
__global__ __launch_bounds__(NTHR, 3) void lstm_step(int t) {
    __shared__ __align__(16) float As[STAGES][KB][BM];
    __shared__ __align__(16) float Bs[STAGES][KB][BN];

    const int tid = threadIdx.x;
    const int tx = tid & 7;        // 8 col-groups of 16
    const int ty = tid >> 3;       // 16 row-groups of 8
    const int rowbase = blockIdx.x * BM;
    const int sbase = blockIdx.y * BN;
    const int hbase = blockIdx.y * 32;
    const int kk = tid >> 4;       // 0..7 : k-row for cp
    const int lane = tid & 15;     // 0..15: 8-float chunk

    const float *A0, *B0, *A1, *B1;
    int K0TILES;
    if (LAYER == 0) {
        A0 = g_featsT + (size_t)t * NIN * NB;
        B0 = g_Wc_t;
        K0TILES = NIN / KB;                       // 2
        A1 = g_hT[0][t & 1];
        B1 = g_Whh_t[0];
    } else {
        A0 = g_hT[0][(t + 1) & 1];
        B0 = g_Wih1_t;
        K0TILES = HH / KB;                        // 32
        A1 = g_hT[1][t & 1];
        B1 = g_Whh_t[1];
    }
    const int TK = K0TILES + HH / KB;

    float acc[8][16];
    #pragma unroll
    for (int i = 0; i < 8; i++)
        #pragma unroll
        for (int j = 0; j < 16; j++) acc[i][j] = 0.0f;

    // prologue: stages 0 and 1 in flight
    issue_tile(A0, B0, A1, B1, K0TILES, 0, 0, As, Bs, rowbase, sbase, kk, lane);
    issue_tile(A0, B0, A1, B1, K0TILES, 1, 1, As, Bs, rowbase, sbase, kk, lane);

    int st = 0, ist = 2;
    for (int kt = 0; kt < TK; kt++) {
        if (kt == TK - 1) asm volatile("cp.async.wait_group 0;");
        else              asm volatile("cp.async.wait_group 1;");
        __syncthreads();

        #pragma unroll
        for (int k = 0; k < KB; k++) {
            float a[8];
            *(float4*)&a[0] = *(const float4*)&As[st][k][ty * 8];
            *(float4*)&a[4] = *(const float4*)&As[st][k][ty * 8 + 4];
            #pragma unroll
            for (int q = 0; q < 4; q++) {
                float4 b = *(const float4*)&Bs[st][k][tx * 16 + q * 4];
                #pragma unroll
                for (int i = 0; i < 8; i++) {
                    acc[i][q * 4 + 0] = fmaf(a[i], b.x, acc[i][q * 4 + 0]);
                    acc[i][q * 4 + 1] = fmaf(a[i], b.y, acc[i][q * 4 + 1]);
                    acc[i][q * 4 + 2] = fmaf(a[i], b.z, acc[i][q * 4 + 2]);
                    acc[i][q * 4 + 3] = fmaf(a[i], b.w, acc[i][q * 4 + 3]);
                }
            }
        }

        if (kt + 2 < TK)
            issue_tile(A0, B0, A1, B1, K0TILES, kt + 2, ist, As, Bs,
                       rowbase, sbase, kk, lane);
        st++;  if (st == STAGES)  st = 0;
        ist++; if (ist == STAGES) ist = 0;
    }

    // ---- LSTM cell epilogue (transposed state layout) ----
    float* cbase = g_cT[LAYER];
    float* hout = g_hT[LAYER][(t + 1) & 1];
    float bsv[16];
    #pragma unroll
    for (int j = 0; j < 16; j++)
        bsv[j] = g_bias[LAYER][sbase + tx * 16 + j];

    #pragma unroll
    for (int jg = 0; jg < 4; jg++) {
        int hcol = hbase + tx * 4 + jg;
        size_t off = (size_t)hcol * NB + rowbase + ty * 8;
        float4 c0 = *(const float4*)(cbase + off);
        float4 c1 = *(const float4*)(cbase + off + 4);
        float cv[8] = {c0.x, c0.y, c0.z, c0.w, c1.x, c1.y, c1.z, c1.w};
        float cn[8], hn[8];
        #pragma unroll
        for (int i = 0; i < 8; i++) {
            float iv = sigm(acc[i][jg * 4 + 0] + bsv[jg * 4 + 0]);
            float fv = sigm(acc[i][jg * 4 + 1] + bsv[jg * 4 + 1]);
            float gv = tanh_fast(acc[i][jg * 4 + 2] + bsv[jg * 4 + 2]);
            float ov = sigm(acc[i][jg * 4 + 3] + bsv[jg * 4 + 3]);
            cn[i] = fv * cv[i] + iv * gv;
            hn[i] = ov * tanh_fast(cn[i]);
        }
        *(float4*)(cbase + off)     = make_float4(cn[0], cn[1], cn[2], cn[3]);
        *(float4*)(cbase + off + 4) = make_float4(cn[4], cn[5], cn[6], cn[7]);
        *(float4*)(hout + off)      = make_float4(hn[0], hn[1], hn[2], hn[3]);
        *(float4*)(hout + off + 4)  = make_float4(hn[4], hn[5], hn[6], hn[7]);
    }
}

// ---------------------------------------------------------------------------
// Output: tiled transpose [H][N] -> [N][H] for h0,h1,c0,c1
// ---------------------------------------------------------------------------
__global__ void write_out(float* __restrict__ out) {
    __shared__ float tile[32][33];
    const int sec = blockIdx.z;
    const float* src;
    if (sec == 0)      src = g_hT[0][0];
    else if (sec == 1) src = g_hT[1][0];
    else if (sec == 2) src = g_cT[0];
    else               src = g_cT[1];

    const int nb = blockIdx.x * 32;
    const int hb = blockIdx.y * 32;
    const int txx = threadIdx.x;
    const int tyy = threadIdx.y;

    #pragma unroll
    for (int k = 0; k < 4; k++)
        tile[tyy + k * 8][txx] = src[(size_t)(hb + tyy + k * 8) * NB + nb + txx];
    __syncthreads();
    float* dst = out + (size_t)sec * NB * HH;
    #pragma unroll
    for (int k = 0; k < 4; k++)
        dst[(size_t)(nb + tyy + k * 8) * HH + hb + txx] = tile[txx][tyy + k * 8];
}

// ---------------------------------------------------------------------------
extern "C" void kernel_launch(void* const* d_in, const int* in_sizes, int n_in,
                              void* d_out, int out_size) {
    const float* x       = (const float*)d_in[0];
    const float* coords  = (const float*)d_in[1];
    const float* env     = (const float*)d_in[2];
    const float* areas   = (const float*)d_in[3];
    const float* bird_uv = (const float*)d_in[4];
    const float* W_in    = (const float*)d_in[5];
    const float* W_ih    = (const float*)d_in[6];
    const float* W_hh    = (const float*)d_in[7];
    const float* b_ih    = (const float*)d_in[8];
    const float* b_hh    = (const float*)d_in[9];
    (void)in_sizes; (void)n_in; (void)out_size;

    zero_kernel<<<1024, 256>>>();
    prep_feats<<<2048, 256>>>(x, coords, env, areas, bird_uv);
    prep_transpose<<<768, 256>>>(W_ih, W_hh, b_ih, b_hh);
    prep_wc<<<64, 256>>>(W_in, W_ih);

    dim3 grid(NB / BM, FOURH / BN);   // (64, 8)
    for (int t = 0; t < TT; t++) {
        lstm_step<0><<<grid, NTHR>>>(t);
        lstm_step<1><<<grid, NTHR>>>(t);
    }

    dim3 tgrid(NB / 32, HH / 32, 4);
    write_out<<<tgrid, dim3(32, 8)>>>((float*)d_out);
}

// round 5
// speedup vs baseline: 2.4707x; 2.4707x over previous
#include <cuda_runtime.h>
#include <math.h>

// Problem constants
#define NB    8192
#define TT    48
#define HH    256
#define NENV  10
#define NIN   16
#define FOURH 1024

// GEMM tile config: 128x128 block, 256 threads, 8x8 per thread (split 4+4),
// KB=8, 3-stage cp.async pipeline, one __syncthreads per k-tile.
#define BM     128
#define BN     128
#define KB     8
#define STAGES 3
#define NTHR   256

// ---------------------------------------------------------------------------
// Scratch (static device globals)
// ---------------------------------------------------------------------------
__device__ __align__(256) float g_hT[2][2][HH * NB];     // [layer][pp][h][n]
__device__ __align__(256) float g_cT[2][HH * NB];        // [layer][h][n]
__device__ __align__(256) float g_featsT[TT * NIN * NB]; // [t][f][n]
__device__ __align__(256) float g_Whh_t[2][HH * FOURH];  // [k*1024+s], s=h*4+g
__device__ __align__(256) float g_Wih1_t[HH * FOURH];
__device__ __align__(256) float g_Wc_t[NIN * FOURH];     // folded W_ih0 @ W_in
__device__ __align__(256) float g_bias[2][FOURH];

__device__ __forceinline__ float sigm(float v) {
    return 1.0f / (1.0f + __expf(-v));
}
__device__ __forceinline__ float tanh_fast(float v) {
    return 2.0f / (1.0f + __expf(-2.0f * v)) - 1.0f;
}

// ---------------------------------------------------------------------------
// Prep kernels
// ---------------------------------------------------------------------------
__global__ void zero_kernel() {
    const size_t tot = (size_t)HH * NB;
    for (size_t i = (size_t)blockIdx.x * blockDim.x + threadIdx.x; i < tot;
         i += (size_t)gridDim.x * blockDim.x) {
        g_hT[0][0][i] = 0.0f;
        g_hT[1][0][i] = 0.0f;
        g_cT[0][i] = 0.0f;
        g_cT[1][i] = 0.0f;
    }
}

__global__ void prep_feats(const float* __restrict__ x,
                           const float* __restrict__ coords,
                           const float* __restrict__ env,
                           const float* __restrict__ areas,
                           const float* __restrict__ bird_uv) {
    const int tot = TT * NIN * NB;
    for (int idx = blockIdx.x * blockDim.x + threadIdx.x; idx < tot;
         idx += gridDim.x * blockDim.x) {
        int n = idx & (NB - 1);
        int f = (idx >> 13) & 15;
        int t = idx >> 17;
        float v;
        if (f == 0)       v = x[(size_t)n * TT + t];
        else if (f <= 2)  v = coords[n * 2 + (f - 1)];
        else if (f <= 12) v = env[((size_t)n * NENV + (f - 3)) * TT + t];
        else if (f == 13) v = areas[n];
        else              v = bird_uv[((size_t)n * 2 + (f - 14)) * TT + t];
        g_featsT[idx] = v;
    }
}

// Weights -> [k][s] layout, s = h*4+gate (gate order i,f,g,o); biases combined
__global__ void prep_transpose(const float* __restrict__ W_ih,
                               const float* __restrict__ W_hh,
                               const float* __restrict__ b_ih,
                               const float* __restrict__ b_hh) {
    const int tot = 262144 * 3 + 2048;
    for (int i = blockIdx.x * blockDim.x + threadIdx.x; i < tot;
         i += gridDim.x * blockDim.x) {
        if (i < 524288) {
            int l = i >> 18;
            int r = i & 262143;
            int k = r >> 10;
            int s = r & 1023;
            int g = s & 3;
            int h = s >> 2;
            g_Whh_t[l][r] = W_hh[l * 262144 + (g * HH + h) * HH + k];
        } else if (i < 786432) {
            int r = i - 524288;
            int k = r >> 10;
            int s = r & 1023;
            int g = s & 3;
            int h = s >> 2;
            g_Wih1_t[r] = W_ih[262144 + (g * HH + h) * HH + k];
        } else {
            int j = i - 786432;
            int l = j >> 10;
            int s = j & 1023;
            int g = s & 3;
            int h = s >> 2;
            int row = l * FOURH + g * HH + h;
            g_bias[l][s] = b_ih[row] + b_hh[row];
        }
    }
}

__global__ void prep_wc(const float* __restrict__ W_in,
                        const float* __restrict__ W_ih) {
    int i = blockIdx.x * blockDim.x + threadIdx.x;
    if (i >= NIN * FOURH) return;
    int f = i & 15;
    int s = i >> 4;
    int g = s & 3;
    int h = s >> 2;
    const float* wr = W_ih + (g * HH + h) * HH;
    float acc = 0.0f;
    #pragma unroll 8
    for (int k = 0; k < HH; k++)
        acc = fmaf(wr[k], W_in[k * NIN + f], acc);
    g_Wc_t[f * FOURH + s] = acc;
}

// ---------------------------------------------------------------------------
// Fused LSTM step
// ---------------------------------------------------------------------------
__device__ __forceinline__ void issue_tile(const float* __restrict__ A0,
                                           const float* __restrict__ B0,
                                           const float* __restrict__ A1,
                                           const float* __restrict__ B1,
                                           int K0TILES, int j, int st,
                                           float (*As)[KB][BM],
                                           float (*Bs)[KB][BN],
                                           int rowbase, int sbase,
                                           int lrow, int lcol) {
    const float* Ab;
    const float* Bb;
    int kl;
    if (j < K0TILES) { Ab = A0; Bb = B0; kl = j; }
    else             { Ab = A1; Bb = B1; kl = j - K0TILES; }
    const float* asrc = Ab + (size_t)(kl * KB + lrow) * NB + rowbase + lcol;
    const float* bsrc = Bb + (size_t)(kl * KB + lrow) * FOURH + sbase + lcol;
    unsigned ad = (unsigned)__cvta_generic_to_shared(&As[st][lrow][lcol]);
    unsigned bd = (unsigned)__cvta_generic_to_shared(&Bs[st][lrow][lcol]);
    asm volatile(
        "cp.async.cg.shared.global [%0], [%1], 16;\n"
        "cp.async.cg.shared.global [%2], [%3], 16;\n"
        :: "r"(ad), "l"(asrc), "r"(bd), "l"(bsrc));
    asm volatile("cp.async.commit_group;");
}

template <int LAYER>
__global__ __launch_bounds__(NTHR, 2) void lstm_step(int t) {
    __shared__ __align__(16) float As[STAGES][KB][BM];
    __shared__ __align__(16) float Bs[STAGES][KB][BN];

    const int tid = threadIdx.x;
    const int tx = tid & 15;       // 16 col groups; cols {tx*4..+3, 64+tx*4..+3}
    const int ty = tid >> 4;       // 16 row groups; rows {ty*4..+3, 64+ty*4..+3}
    const int rowbase = blockIdx.x * BM;
    const int sbase = blockIdx.y * BN;
    const int hbase = blockIdx.y * 32;
    const int lrow = tid >> 5;     // 0..7  cp.async k-row
    const int lcol = (tid & 31) * 4; // 0..124 cp.async 4-float chunk

    const float *A0, *B0, *A1, *B1;
    int K0TILES;
    if (LAYER == 0) {
        A0 = g_featsT + (size_t)t * NIN * NB;
        B0 = g_Wc_t;
        K0TILES = NIN / KB;                       // 2
        A1 = g_hT[0][t & 1];
        B1 = g_Whh_t[0];
    } else {
        A0 = g_hT[0][(t + 1) & 1];
        B0 = g_Wih1_t;
        K0TILES = HH / KB;                        // 32
        A1 = g_hT[1][t & 1];
        B1 = g_Whh_t[1];
    }
    const int TK = K0TILES + HH / KB;

    float acc[8][8];
    #pragma unroll
    for (int i = 0; i < 8; i++)
        #pragma unroll
        for (int j = 0; j < 8; j++) acc[i][j] = 0.0f;

    issue_tile(A0, B0, A1, B1, K0TILES, 0, 0, As, Bs, rowbase, sbase, lrow, lcol);
    issue_tile(A0, B0, A1, B1, K0TILES, 1, 1, As, Bs, rowbase, sbase, lrow, lcol);

    int st = 0, ist = 2;
    for (int kt = 0; kt < TK; kt++) {
        if (kt == TK - 1) asm volatile("cp.async.wait_group 0;");
        else              asm volatile("cp.async.wait_group 1;");
        __syncthreads();

        #pragma unroll
        for (int k = 0; k < KB; k++) {
            float a[8], b[8];
            *(float4*)&a[0] = *(const float4*)&As[st][k][ty * 4];
            *(float4*)&a[4] = *(const float4*)&As[st][k][64 + ty * 4];
            *(float4*)&b[0] = *(const float4*)&Bs[st][k][tx * 4];
            *(float4*)&b[4] = *(const float4*)&Bs[st][k][64 + tx * 4];
            #pragma unroll
            for (int i = 0; i < 8; i++)
                #pragma unroll
                for (int j = 0; j < 8; j++)
                    acc[i][j] = fmaf(a[i], b[j], acc[i][j]);
        }

        if (kt + 2 < TK)
            issue_tile(A0, B0, A1, B1, K0TILES, kt + 2, ist, As, Bs,
                       rowbase, sbase, lrow, lcol);
        st++;  if (st == STAGES)  st = 0;
        ist++; if (ist == STAGES) ist = 0;
    }

    // ---- LSTM cell epilogue (transposed state layout) ----
    float* cbase = g_cT[LAYER];
    float* hout = g_hT[LAYER][(t + 1) & 1];
    float bsv[8];
    #pragma unroll
    for (int j = 0; j < 4; j++) {
        bsv[j]     = g_bias[LAYER][sbase + tx * 4 + j];
        bsv[4 + j] = g_bias[LAYER][sbase + 64 + tx * 4 + j];
    }

    #pragma unroll
    for (int ch = 0; ch < 2; ch++) {
        int hcol = hbase + ch * 16 + tx;
        #pragma unroll
        for (int rh = 0; rh < 2; rh++) {
            size_t off = (size_t)hcol * NB + rowbase + rh * 64 + ty * 4;
            float4 c4 = *(const float4*)(cbase + off);
            float cv[4] = {c4.x, c4.y, c4.z, c4.w};
            float cn[4], hn[4];
            #pragma unroll
            for (int ii = 0; ii < 4; ii++) {
                int i = rh * 4 + ii;
                float iv = sigm(acc[i][ch * 4 + 0] + bsv[ch * 4 + 0]);
                float fv = sigm(acc[i][ch * 4 + 1] + bsv[ch * 4 + 1]);
                float gv = tanh_fast(acc[i][ch * 4 + 2] + bsv[ch * 4 + 2]);
                float ov = sigm(acc[i][ch * 4 + 3] + bsv[ch * 4 + 3]);
                cn[ii] = fv * cv[ii] + iv * gv;
                hn[ii] = ov * tanh_fast(cn[ii]);
            }
            *(float4*)(cbase + off) = make_float4(cn[0], cn[1], cn[2], cn[3]);
            *(float4*)(hout + off)  = make_float4(hn[0], hn[1], hn[2], hn[3]);
        }
    }
}

// ---------------------------------------------------------------------------
// Output: tiled transpose [H][N] -> [N][H] for h0,h1,c0,c1
// ---------------------------------------------------------------------------
__global__ void write_out(float* __restrict__ out) {
    __shared__ float tile[32][33];
    const int sec = blockIdx.z;
    const float* src;
    if (sec == 0)      src = g_hT[0][0];
    else if (sec == 1) src = g_hT[1][0];
    else if (sec == 2) src = g_cT[0];
    else               src = g_cT[1];

    const int nb = blockIdx.x * 32;
    const int hb = blockIdx.y * 32;
    const int txx = threadIdx.x;
    const int tyy = threadIdx.y;

    #pragma unroll
    for (int k = 0; k < 4; k++)
        tile[tyy + k * 8][txx] = src[(size_t)(hb + tyy + k * 8) * NB + nb + txx];
    __syncthreads();
    float* dst = out + (size_t)sec * NB * HH;
    #pragma unroll
    for (int k = 0; k < 4; k++)
        dst[(size_t)(nb + tyy + k * 8) * HH + hb + txx] = tile[txx][tyy + k * 8];
}

// ---------------------------------------------------------------------------
extern "C" void kernel_launch(void* const* d_in, const int* in_sizes, int n_in,
                              void* d_out, int out_size) {
    const float* x       = (const float*)d_in[0];
    const float* coords  = (const float*)d_in[1];
    const float* env     = (const float*)d_in[2];
    const float* areas   = (const float*)d_in[3];
    const float* bird_uv = (const float*)d_in[4];
    const float* W_in    = (const float*)d_in[5];
    const float* W_ih    = (const float*)d_in[6];
    const float* W_hh    = (const float*)d_in[7];
    const float* b_ih    = (const float*)d_in[8];
    const float* b_hh    = (const float*)d_in[9];
    (void)in_sizes; (void)n_in; (void)out_size;

    zero_kernel<<<1024, 256>>>();
    prep_feats<<<2048, 256>>>(x, coords, env, areas, bird_uv);
    prep_transpose<<<768, 256>>>(W_ih, W_hh, b_ih, b_hh);
    prep_wc<<<64, 256>>>(W_in, W_ih);

    dim3 grid(NB / BM, FOURH / BN);   // (64, 8)
    for (int t = 0; t < TT; t++) {
        lstm_step<0><<<grid, NTHR>>>(t);
        lstm_step<1><<<grid, NTHR>>>(t);
    }

    dim3 tgrid(NB / 32, HH / 32, 4);
    write_out<<<tgrid, dim3(32, 8)>>>((float*)d_out);
}

// round 8
// speedup vs baseline: 5.6772x; 2.2978x over previous
#include <cuda_runtime.h>
#include <cstdint>
#include <math.h>

// Problem constants
#define NB    8192
#define TT    48
#define HH    256
#define NENV  10
#define FOURH 1024
#define KPAD  32

// MMA tile config: CTA 128x128, 8 warps (2x4), warp tile 64x32, m16n8k8 tf32
#define BM    128
#define BN    128            // gate-cols per CTA (= 32 h)
#define KT    32             // k per stage
#define LDA   36             // padded smem row stride (floats) -> conflict-free frags
#define A_WORDS (BM * LDA)   // 4608 floats (A tile == B tile size)
#define STAGE_WORDS (2 * A_WORDS)
#define CS_WORDS (BM * LDA)
#define SMEM_DYN ((2 * STAGE_WORDS + CS_WORDS) * 4)   // 92160 B

// ---------------------------------------------------------------------------
// Scratch
// ---------------------------------------------------------------------------
__device__ __align__(256) float g_h[2][2][NB * HH];      // [layer][pp][n][h]
__device__ __align__(256) float g_c[2][NB * HH];         // [layer][n][h]
__device__ __align__(256) float g_featsP[TT * NB * KPAD]; // [t][n][32] (pad 0)
__device__ __align__(256) float g_WhhP[2][FOURH * HH];   // [r_perm][k]
__device__ __align__(256) float g_Wih1P[FOURH * HH];
__device__ __align__(256) float g_WcP[FOURH * KPAD];     // folded W_ih0 @ W_in
__device__ __align__(256) float g_bias[2][FOURH];        // ORIGINAL layout g*256+h

__device__ __forceinline__ float sigm(float v) {
    return 1.0f / (1.0f + __expf(-v));
}
__device__ __forceinline__ float tanh_fast(float v) {
    return 2.0f / (1.0f + __expf(-2.0f * v)) - 1.0f;
}
__device__ __forceinline__ float to_tf32(float x) {
    float y;
    asm("cvt.rna.tf32.f32 %0, %1;" : "=f"(y) : "f"(x));
    return y;
}
__device__ __forceinline__ uint32_t smem_u32(const void* p) {
    return (uint32_t)__cvta_generic_to_shared(p);
}

// Column permutation sigma: permuted gate-row r -> original row (gate*256 + h).
// Within each 128-col block: h_local = (c>>4)*4 + ((c>>1)&3),
//                            gate    = ((c>>3)&1)*2 + (c&1)
__host__ __device__ __forceinline__ int sigma_orig(int r) {
    int blk = r >> 7;
    int c = r & 127;
    int h = blk * 32 + ((c >> 4) << 2) + ((c >> 1) & 3);
    int gate = (((c >> 3) & 1) << 1) | (c & 1);
    return gate * HH + h;
}

// ---------------------------------------------------------------------------
// Prep kernels
// ---------------------------------------------------------------------------
__global__ void zero_kernel() {
    const size_t tot = (size_t)NB * HH;
    for (size_t i = (size_t)blockIdx.x * blockDim.x + threadIdx.x; i < tot;
         i += (size_t)gridDim.x * blockDim.x) {
        g_h[0][0][i] = 0.0f;
        g_h[1][0][i] = 0.0f;
        g_c[0][i] = 0.0f;
        g_c[1][i] = 0.0f;
    }
}

__global__ void prep_feats(const float* __restrict__ x,
                           const float* __restrict__ coords,
                           const float* __restrict__ env,
                           const float* __restrict__ areas,
                           const float* __restrict__ bird_uv) {
    const int tot = TT * NB * KPAD;
    for (int idx = blockIdx.x * blockDim.x + threadIdx.x; idx < tot;
         idx += gridDim.x * blockDim.x) {
        int f = idx & 31;
        int n = (idx >> 5) & (NB - 1);
        int t = idx >> 18;
        float v = 0.0f;
        if (f == 0)       v = x[(size_t)n * TT + t];
        else if (f <= 2)  v = coords[n * 2 + (f - 1)];
        else if (f <= 12) v = env[((size_t)n * NENV + (f - 3)) * TT + t];
        else if (f == 13) v = areas[n];
        else if (f <= 15) v = bird_uv[((size_t)n * 2 + (f - 14)) * TT + t];
        g_featsP[idx] = to_tf32(v);
    }
}

// Permute weight rows by sigma, tf32-round; biases kept in original layout.
__global__ void prep_weights(const float* __restrict__ W_ih,
                             const float* __restrict__ W_hh,
                             const float* __restrict__ b_ih,
                             const float* __restrict__ b_hh) {
    const int tot = 524288 + 262144 + 2048;
    for (int i = blockIdx.x * blockDim.x + threadIdx.x; i < tot;
         i += gridDim.x * blockDim.x) {
        if (i < 524288) {
            int l = i >> 18;
            int rem = i & 262143;
            int r = rem >> 8;
            int k = rem & 255;
            int orig = sigma_orig(r);
            g_WhhP[l][rem] = to_tf32(W_hh[l * 262144 + orig * HH + k]);
        } else if (i < 786432) {
            int rem = i - 524288;
            int r = rem >> 8;
            int k = rem & 255;
            int orig = sigma_orig(r);
            g_Wih1P[rem] = to_tf32(W_ih[262144 + orig * HH + k]);
        } else {
            int j = i - 786432;
            int l = j >> 10;
            int s = j & 1023;
            g_bias[l][s] = b_ih[l * FOURH + s] + b_hh[l * FOURH + s];
        }
    }
}

// Folded Wc = W_ih0 @ W_in, sigma-permuted rows, k padded to 32
__global__ void prep_wc(const float* __restrict__ W_in,
                        const float* __restrict__ W_ih) {
    int i = blockIdx.x * blockDim.x + threadIdx.x;
    if (i >= FOURH * KPAD) return;
    int k = i & 31;
    int r = i >> 5;
    float out = 0.0f;
    if (k < 16) {
        int orig = sigma_orig(r);
        const float* wr = W_ih + orig * HH;   // layer 0
        float acc = 0.0f;
        #pragma unroll 8
        for (int m = 0; m < HH; m++)
            acc = fmaf(wr[m], W_in[m * 16 + k], acc);
        out = to_tf32(acc);
    }
    g_WcP[i] = out;
}

// ---------------------------------------------------------------------------
// Fused mma.sync tf32 LSTM step
// ---------------------------------------------------------------------------
__device__ __forceinline__ void issue_tile(const float* __restrict__ Ab, int as,
                                           const float* __restrict__ Bb, int bs,
                                           int k0, float* dynbase, int st,
                                           int rowbase, int gbase, int tid) {
    float* As = dynbase + st * STAGE_WORDS;
    float* Bs = As + A_WORDS;
    #pragma unroll
    for (int j = 0; j < 4; j++) {
        int idx = tid + j * 256;
        int row = idx >> 3, ch = idx & 7;
        const float* srca = Ab + (size_t)(rowbase + row) * as + k0 + ch * 4;
        const float* srcb = Bb + (size_t)(gbase + row) * bs + k0 + ch * 4;
        uint32_t da = smem_u32(As + row * LDA + ch * 4);
        uint32_t db = smem_u32(Bs + row * LDA + ch * 4);
        asm volatile(
            "cp.async.cg.shared.global [%0], [%1], 16;\n"
            "cp.async.cg.shared.global [%2], [%3], 16;\n"
            :: "r"(da), "l"(srca), "r"(db), "l"(srcb));
    }
    asm volatile("cp.async.commit_group;");
}

__device__ __forceinline__ void mma_tf32(float* d, const uint32_t* a,
                                         const uint32_t* b) {
    asm volatile(
        "mma.sync.aligned.m16n8k8.row.col.f32.tf32.tf32.f32 "
        "{%0,%1,%2,%3}, {%4,%5,%6,%7}, {%8,%9}, {%0,%1,%2,%3};"
        : "+f"(d[0]), "+f"(d[1]), "+f"(d[2]), "+f"(d[3])
        : "r"(a[0]), "r"(a[1]), "r"(a[2]), "r"(a[3]), "r"(b[0]), "r"(b[1]));
}

template <int LAYER>
__global__ __launch_bounds__(256, 2) void lstm_step_mma(int t) {
    extern __shared__ __align__(16) float dyn[];
    float* Cs = dyn + 2 * STAGE_WORDS;

    const int tid = threadIdx.x;
    const int wid = tid >> 5;
    const int lane = tid & 31;
    const int gid = lane >> 2;
    const int tig = lane & 3;
    const int wm = (wid & 1) * 64;        // warp row base (within CTA)
    const int wn = (wid >> 1) * 32;       // warp col base (gate cols)
    const int rowbase = blockIdx.x * BM;
    const int gbase = blockIdx.y * BN;
    const int hb = blockIdx.y * 32;

    // --- prefetch old c tile (coalesced) as first cp.async group ---
    {
        const float* cg = g_c[LAYER] + (size_t)rowbase * HH + hb;
        #pragma unroll
        for (int j = 0; j < 4; j++) {
            int idx = tid + j * 256;
            int row = idx >> 3, ch = idx & 7;
            const float* src = cg + (size_t)row * HH + ch * 4;
            uint32_t d = smem_u32(Cs + row * LDA + ch * 4);
            asm volatile("cp.async.cg.shared.global [%0], [%1], 16;"
                         :: "r"(d), "l"(src));
        }
        asm volatile("cp.async.commit_group;");
    }

    // --- operand selection ---
    const float *A0, *B0, *A1, *B1;
    int a0s, b0s, K0T;
    if (LAYER == 0) {
        A0 = g_featsP + (size_t)t * NB * KPAD;  a0s = KPAD;
        B0 = g_WcP;                              b0s = KPAD;
        K0T = 1;
        A1 = g_h[0][t & 1];
        B1 = g_WhhP[0];
    } else {
        A0 = g_h[0][(t + 1) & 1];                a0s = HH;
        B0 = g_Wih1P;                            b0s = HH;
        K0T = HH / KT;                           // 8
        A1 = g_h[1][t & 1];
        B1 = g_WhhP[1];
    }
    const int TK = K0T + HH / KT;

    float acc[4][4][4];
    #pragma unroll
    for (int i = 0; i < 4; i++)
        #pragma unroll
        for (int j = 0; j < 4; j++)
            #pragma unroll
            for (int k = 0; k < 4; k++) acc[i][j][k] = 0.0f;

    // prologue: stages 0 and 1
    issue_tile(A0, a0s, B0, b0s, 0, dyn, 0, rowbase, gbase, tid);
    {
        const float* Ab = (1 < K0T) ? A0 : A1;
        const float* Bb = (1 < K0T) ? B0 : B1;
        int as = (1 < K0T) ? a0s : HH;
        int bs = (1 < K0T) ? b0s : HH;
        int k0 = (1 < K0T) ? KT : 0;
        issue_tile(Ab, as, Bb, bs, k0, dyn, 1, rowbase, gbase, tid);
    }

    for (int kt = 0; kt < TK; kt++) {
        if (kt == TK - 1) asm volatile("cp.async.wait_group 0;");
        else              asm volatile("cp.async.wait_group 1;");
        __syncthreads();

        const uint32_t* Asu = (const uint32_t*)(dyn + (kt & 1) * STAGE_WORDS);
        const uint32_t* Bsu = Asu + A_WORDS;

        #pragma unroll
        for (int kk = 0; kk < 4; kk++) {
            const int kb = kk * 8;
            uint32_t a[4][4];
            #pragma unroll
            for (int mt = 0; mt < 4; mt++) {
                int r0 = (wm + mt * 16 + gid) * LDA + kb + tig;
                a[mt][0] = Asu[r0];
                a[mt][1] = Asu[r0 + 8 * LDA];
                a[mt][2] = Asu[r0 + 4];
                a[mt][3] = Asu[r0 + 8 * LDA + 4];
            }
            uint32_t b[4][2];
            #pragma unroll
            for (int nt = 0; nt < 4; nt++) {
                int c0 = (wn + nt * 8 + gid) * LDA + kb + tig;
                b[nt][0] = Bsu[c0];
                b[nt][1] = Bsu[c0 + 4];
            }
            #pragma unroll
            for (int mt = 0; mt < 4; mt++)
                #pragma unroll
                for (int nt = 0; nt < 4; nt++)
                    mma_tf32(acc[mt][nt], a[mt], b[nt]);
        }

        __syncthreads();
        if (kt + 2 < TK) {
            int j = kt + 2;
            const float *Ab, *Bb;
            int as, bs, k0;
            if (j < K0T) { Ab = A0; Bb = B0; as = a0s; bs = b0s; k0 = j * KT; }
            else         { Ab = A1; Bb = B1; as = HH;  bs = HH;  k0 = (j - K0T) * KT; }
            issue_tile(Ab, as, Bb, bs, k0, dyn, kt & 1, rowbase, gbase, tid);
        }
    }

    // --- LSTM cell epilogue (register fragments -> smem staging) ---
    float* Hs = dyn;   // alias stage 0 (all compute done)
    int hq[2];
    float bb[2][4];
    #pragma unroll
    for (int q = 0; q < 2; q++) {
        int hl = ((wid >> 1) * 2 + q) * 4 + tig;
        hq[q] = hl;
        #pragma unroll
        for (int g = 0; g < 4; g++)
            bb[q][g] = g_bias[LAYER][g * HH + hb + hl];
    }

    #pragma unroll
    for (int mt = 0; mt < 4; mt++)
        #pragma unroll
        for (int q = 0; q < 2; q++)
            #pragma unroll
            for (int rr = 0; rr < 2; rr++) {
                int row = wm + mt * 16 + gid + rr * 8;
                float iv = sigm(acc[mt][2 * q][rr * 2 + 0] + bb[q][0]);
                float fv = sigm(acc[mt][2 * q][rr * 2 + 1] + bb[q][1]);
                float gv = tanh_fast(acc[mt][2 * q + 1][rr * 2 + 0] + bb[q][2]);
                float ov = sigm(acc[mt][2 * q + 1][rr * 2 + 1] + bb[q][3]);
                float co = Cs[row * LDA + hq[q]];
                float cn = fv * co + iv * gv;
                float hn = to_tf32(ov * tanh_fast(cn));
                Cs[row * LDA + hq[q]] = cn;
                Hs[row * LDA + hq[q]] = hn;
            }
    __syncthreads();

    // --- coalesced write-out ---
    float* hg = g_h[LAYER][(t + 1) & 1] + (size_t)rowbase * HH + hb;
    float* cg = g_c[LAYER] + (size_t)rowbase * HH + hb;
    #pragma unroll
    for (int j = 0; j < 4; j++) {
        int idx = tid + j * 256;
        int row = idx >> 3, ch = idx & 7;
        *(float4*)(hg + (size_t)row * HH + ch * 4) =
            *(const float4*)&Hs[row * LDA + ch * 4];
        *(float4*)(cg + (size_t)row * HH + ch * 4) =
            *(const float4*)&Cs[row * LDA + ch * 4];
    }
}

// ---------------------------------------------------------------------------
// Output: straight copy [h0, h1, c0, c1]
// ---------------------------------------------------------------------------
__global__ void write_out(float* __restrict__ out, size_t out_elems) {
    const size_t NH = (size_t)NB * HH;
    for (size_t i = (size_t)blockIdx.x * blockDim.x + threadIdx.x;
         i < out_elems; i += (size_t)gridDim.x * blockDim.x) {
        size_t sec = i / NH;
        size_t r = i - sec * NH;
        float v;
        if (sec == 0)      v = g_h[0][0][r];
        else if (sec == 1) v = g_h[1][0][r];
        else if (sec == 2) v = g_c[0][r];
        else               v = g_c[1][r];
        out[i] = v;
    }
}

// ---------------------------------------------------------------------------
extern "C" void kernel_launch(void* const* d_in, const int* in_sizes, int n_in,
                              void* d_out, int out_size) {
    const float* x       = (const float*)d_in[0];
    const float* coords  = (const float*)d_in[1];
    const float* env     = (const float*)d_in[2];
    const float* areas   = (const float*)d_in[3];
    const float* bird_uv = (const float*)d_in[4];
    const float* W_in    = (const float*)d_in[5];
    const float* W_ih    = (const float*)d_in[6];
    const float* W_hh    = (const float*)d_in[7];
    const float* b_ih    = (const float*)d_in[8];
    const float* b_hh    = (const float*)d_in[9];
    (void)in_sizes; (void)n_in;

    cudaFuncSetAttribute(lstm_step_mma<0>,
                         cudaFuncAttributeMaxDynamicSharedMemorySize, SMEM_DYN);
    cudaFuncSetAttribute(lstm_step_mma<1>,
                         cudaFuncAttributeMaxDynamicSharedMemorySize, SMEM_DYN);

    zero_kernel<<<1024, 256>>>();
    prep_feats<<<4096, 256>>>(x, coords, env, areas, bird_uv);
    prep_weights<<<768, 256>>>(W_ih, W_hh, b_ih, b_hh);
    prep_wc<<<128, 256>>>(W_in, W_ih);

    dim3 grid(NB / BM, FOURH / BN);   // (64, 8)
    for (int t = 0; t < TT; t++) {
        lstm_step_mma<0><<<grid, 256, SMEM_DYN>>>(t);
        lstm_step_mma<1><<<grid, 256, SMEM_DYN>>>(t);
    }

    write_out<<<4096, 256>>>((float*)d_out, (size_t)out_size);
}

// round 9
// speedup vs baseline: 6.5311x; 1.1504x over previous
#include <cuda_runtime.h>
#include <cstdint>
#include <math.h>

// Problem constants
#define NB    8192
#define TT    48
#define HH    256
#define NENV  10
#define FOURH 1024
#define KPAD  32

// MMA tile config: CTA 128x128, 8 warps (2x4), warp tile 64x32, m16n8k8 tf32
#define BM    128
#define BN    128
#define KT    32
#define LDA   36
#define A_WORDS (BM * LDA)
#define STAGE_WORDS (2 * A_WORDS)
#define CS_WORDS (BM * LDA)
#define SMEM_DYN ((2 * STAGE_WORDS + CS_WORDS) * 4)   // 92160 B

// ---------------------------------------------------------------------------
// Scratch
// ---------------------------------------------------------------------------
__device__ __align__(256) float g_h[2][2][NB * HH];      // [layer][pp][n][h]
__device__ __align__(256) float g_c[2][NB * HH];         // [layer][n][h]
__device__ __align__(256) float g_featsP[TT * NB * KPAD]; // [t][n][32] (pad 0)
__device__ __align__(256) float g_WhhP[2][FOURH * HH];   // [r_perm][k]
__device__ __align__(256) float g_Wih1P[FOURH * HH];
__device__ __align__(256) float g_WcP[FOURH * KPAD];     // folded W_ih0 @ W_in
__device__ __align__(256) float g_bias[2][FOURH];        // original layout g*256+h

__device__ __forceinline__ float sigm(float v) {
    return 1.0f / (1.0f + __expf(-v));
}
__device__ __forceinline__ float tanh_fast(float v) {
    return 2.0f / (1.0f + __expf(-2.0f * v)) - 1.0f;
}
__device__ __forceinline__ float to_tf32(float x) {
    float y;
    asm("cvt.rna.tf32.f32 %0, %1;" : "=f"(y) : "f"(x));
    return y;
}
__device__ __forceinline__ uint32_t smem_u32(const void* p) {
    return (uint32_t)__cvta_generic_to_shared(p);
}

// Column permutation sigma: permuted gate-row r -> original row (gate*256 + h)
__host__ __device__ __forceinline__ int sigma_orig(int r) {
    int blk = r >> 7;
    int c = r & 127;
    int h = blk * 32 + ((c >> 4) << 2) + ((c >> 1) & 3);
    int gate = (((c >> 3) & 1) << 1) | (c & 1);
    return gate * HH + h;
}

// ---------------------------------------------------------------------------
// Prep kernels
// ---------------------------------------------------------------------------
__global__ void zero_kernel() {
    const size_t tot = (size_t)NB * HH;
    for (size_t i = (size_t)blockIdx.x * blockDim.x + threadIdx.x; i < tot;
         i += (size_t)gridDim.x * blockDim.x) {
        g_h[0][0][i] = 0.0f;
        g_h[1][0][i] = 0.0f;
        g_c[0][i] = 0.0f;
        g_c[1][i] = 0.0f;
    }
}

__global__ void prep_feats(const float* __restrict__ x,
                           const float* __restrict__ coords,
                           const float* __restrict__ env,
                           const float* __restrict__ areas,
                           const float* __restrict__ bird_uv) {
    const int tot = TT * NB * KPAD;
    for (int idx = blockIdx.x * blockDim.x + threadIdx.x; idx < tot;
         idx += gridDim.x * blockDim.x) {
        int f = idx & 31;
        int n = (idx >> 5) & (NB - 1);
        int t = idx >> 18;
        float v = 0.0f;
        if (f == 0)       v = x[(size_t)n * TT + t];
        else if (f <= 2)  v = coords[n * 2 + (f - 1)];
        else if (f <= 12) v = env[((size_t)n * NENV + (f - 3)) * TT + t];
        else if (f == 13) v = areas[n];
        else if (f <= 15) v = bird_uv[((size_t)n * 2 + (f - 14)) * TT + t];
        g_featsP[idx] = to_tf32(v);
    }
}

__global__ void prep_weights(const float* __restrict__ W_ih,
                             const float* __restrict__ W_hh,
                             const float* __restrict__ b_ih,
                             const float* __restrict__ b_hh) {
    const int tot = 524288 + 262144 + 2048;
    for (int i = blockIdx.x * blockDim.x + threadIdx.x; i < tot;
         i += gridDim.x * blockDim.x) {
        if (i < 524288) {
            int l = i >> 18;
            int rem = i & 262143;
            int r = rem >> 8;
            int k = rem & 255;
            g_WhhP[l][rem] = to_tf32(W_hh[l * 262144 + sigma_orig(r) * HH + k]);
        } else if (i < 786432) {
            int rem = i - 524288;
            int r = rem >> 8;
            int k = rem & 255;
            g_Wih1P[rem] = to_tf32(W_ih[262144 + sigma_orig(r) * HH + k]);
        } else {
            int j = i - 786432;
            int l = j >> 10;
            int s = j & 1023;
            g_bias[l][s] = b_ih[l * FOURH + s] + b_hh[l * FOURH + s];
        }
    }
}

__global__ void prep_wc(const float* __restrict__ W_in,
                        const float* __restrict__ W_ih) {
    int i = blockIdx.x * blockDim.x + threadIdx.x;
    if (i >= FOURH * KPAD) return;
    int k = i & 31;
    int r = i >> 5;
    float out = 0.0f;
    if (k < 16) {
        const float* wr = W_ih + sigma_orig(r) * HH;   // layer 0
        float acc = 0.0f;
        #pragma unroll 8
        for (int m = 0; m < HH; m++)
            acc = fmaf(wr[m], W_in[m * 16 + k], acc);
        out = to_tf32(acc);
    }
    g_WcP[i] = out;
}

// ---------------------------------------------------------------------------
// Fused mma.sync tf32 LSTM wavefront step:
//   blockIdx.z = 0 -> layer 0 at t = k
//   blockIdx.z = 1 -> layer 1 at t = k - 1     (independent of layer0(k))
// ---------------------------------------------------------------------------
__device__ __forceinline__ void issue_tile(const float* __restrict__ Ab, int as,
                                           const float* __restrict__ Bb, int bs,
                                           int k0, float* dynbase, int st,
                                           int rowbase, int gbase, int tid) {
    float* As = dynbase + st * STAGE_WORDS;
    float* Bs = As + A_WORDS;
    #pragma unroll
    for (int j = 0; j < 4; j++) {
        int idx = tid + j * 256;
        int row = idx >> 3, ch = idx & 7;
        const float* srca = Ab + (size_t)(rowbase + row) * as + k0 + ch * 4;
        const float* srcb = Bb + (size_t)(gbase + row) * bs + k0 + ch * 4;
        uint32_t da = smem_u32(As + row * LDA + ch * 4);
        uint32_t db = smem_u32(Bs + row * LDA + ch * 4);
        asm volatile(
            "cp.async.cg.shared.global [%0], [%1], 16;\n"
            "cp.async.cg.shared.global [%2], [%3], 16;\n"
            :: "r"(da), "l"(srca), "r"(db), "l"(srcb));
    }
    asm volatile("cp.async.commit_group;");
}

__device__ __forceinline__ void mma_tf32(float* d, const uint32_t* a,
                                         const uint32_t* b) {
    asm volatile(
        "mma.sync.aligned.m16n8k8.row.col.f32.tf32.tf32.f32 "
        "{%0,%1,%2,%3}, {%4,%5,%6,%7}, {%8,%9}, {%0,%1,%2,%3};"
        : "+f"(d[0]), "+f"(d[1]), "+f"(d[2]), "+f"(d[3])
        : "r"(a[0]), "r"(a[1]), "r"(a[2]), "r"(a[3]), "r"(b[0]), "r"(b[1]));
}

__global__ __launch_bounds__(256, 2) void lstm_step_mma(int kstep,
                                                        float* __restrict__ out) {
    const int layer = blockIdx.z;
    const int t = (layer == 0) ? kstep : kstep - 1;
    if (t < 0 || t >= TT) return;

    extern __shared__ __align__(16) float dyn[];
    float* Cs = dyn + 2 * STAGE_WORDS;

    const int tid = threadIdx.x;
    const int wid = tid >> 5;
    const int lane = tid & 31;
    const int gid = lane >> 2;
    const int tig = lane & 3;
    const int wm = (wid & 1) * 64;
    const int wn = (wid >> 1) * 32;
    const int rowbase = blockIdx.x * BM;
    const int gbase = blockIdx.y * BN;
    const int hb = blockIdx.y * 32;

    // --- prefetch old c tile as first cp.async group ---
    {
        const float* cg = g_c[layer] + (size_t)rowbase * HH + hb;
        #pragma unroll
        for (int j = 0; j < 4; j++) {
            int idx = tid + j * 256;
            int row = idx >> 3, ch = idx & 7;
            const float* src = cg + (size_t)row * HH + ch * 4;
            uint32_t d = smem_u32(Cs + row * LDA + ch * 4);
            asm volatile("cp.async.cg.shared.global [%0], [%1], 16;"
                         :: "r"(d), "l"(src));
        }
        asm volatile("cp.async.commit_group;");
    }

    // --- operand selection ---
    const float *A0, *B0, *A1, *B1;
    int a0s, b0s, K0T;
    if (layer == 0) {
        A0 = g_featsP + (size_t)t * NB * KPAD;  a0s = KPAD;
        B0 = g_WcP;                              b0s = KPAD;
        K0T = 1;
        A1 = g_h[0][t & 1];
        B1 = g_WhhP[0];
    } else {
        A0 = g_h[0][(t + 1) & 1];                a0s = HH;
        B0 = g_Wih1P;                            b0s = HH;
        K0T = HH / KT;                           // 8
        A1 = g_h[1][t & 1];
        B1 = g_WhhP[1];
    }
    const int TK = K0T + HH / KT;

    float acc[4][4][4];
    #pragma unroll
    for (int i = 0; i < 4; i++)
        #pragma unroll
        for (int j = 0; j < 4; j++)
            #pragma unroll
            for (int k = 0; k < 4; k++) acc[i][j][k] = 0.0f;

    // prologue: stages 0 and 1
    issue_tile(A0, a0s, B0, b0s, 0, dyn, 0, rowbase, gbase, tid);
    {
        const float* Ab = (1 < K0T) ? A0 : A1;
        const float* Bb = (1 < K0T) ? B0 : B1;
        int as = (1 < K0T) ? a0s : HH;
        int bs = (1 < K0T) ? b0s : HH;
        int k0 = (1 < K0T) ? KT : 0;
        issue_tile(Ab, as, Bb, bs, k0, dyn, 1, rowbase, gbase, tid);
    }

    for (int kt = 0; kt < TK; kt++) {
        if (kt == TK - 1) asm volatile("cp.async.wait_group 0;");
        else              asm volatile("cp.async.wait_group 1;");
        __syncthreads();

        const uint32_t* Asu = (const uint32_t*)(dyn + (kt & 1) * STAGE_WORDS);
        const uint32_t* Bsu = Asu + A_WORDS;

        #pragma unroll
        for (int kk = 0; kk < 4; kk++) {
            const int kb = kk * 8;
            uint32_t a[4][4];
            #pragma unroll
            for (int mt = 0; mt < 4; mt++) {
                int r0 = (wm + mt * 16 + gid) * LDA + kb + tig;
                a[mt][0] = Asu[r0];
                a[mt][1] = Asu[r0 + 8 * LDA];
                a[mt][2] = Asu[r0 + 4];
                a[mt][3] = Asu[r0 + 8 * LDA + 4];
            }
            uint32_t b[4][2];
            #pragma unroll
            for (int nt = 0; nt < 4; nt++) {
                int c0 = (wn + nt * 8 + gid) * LDA + kb + tig;
                b[nt][0] = Bsu[c0];
                b[nt][1] = Bsu[c0 + 4];
            }
            #pragma unroll
            for (int mt = 0; mt < 4; mt++)
                #pragma unroll
                for (int nt = 0; nt < 4; nt++)
                    mma_tf32(acc[mt][nt], a[mt], b[nt]);
        }

        __syncthreads();
        if (kt + 2 < TK) {
            int j = kt + 2;
            const float *Ab, *Bb;
            int as, bs, k0;
            if (j < K0T) { Ab = A0; Bb = B0; as = a0s; bs = b0s; k0 = j * KT; }
            else         { Ab = A1; Bb = B1; as = HH;  bs = HH;  k0 = (j - K0T) * KT; }
            issue_tile(Ab, as, Bb, bs, k0, dyn, kt & 1, rowbase, gbase, tid);
        }
    }

    // --- LSTM cell epilogue ---
    float* Hs = dyn;   // alias stage 0
    int hq[2];
    float bb[2][4];
    #pragma unroll
    for (int q = 0; q < 2; q++) {
        int hl = ((wid >> 1) * 2 + q) * 4 + tig;
        hq[q] = hl;
        #pragma unroll
        for (int g = 0; g < 4; g++)
            bb[q][g] = g_bias[layer][g * HH + hb + hl];
    }

    #pragma unroll
    for (int mt = 0; mt < 4; mt++)
        #pragma unroll
        for (int q = 0; q < 2; q++)
            #pragma unroll
            for (int rr = 0; rr < 2; rr++) {
                int row = wm + mt * 16 + gid + rr * 8;
                float iv = sigm(acc[mt][2 * q][rr * 2 + 0] + bb[q][0]);
                float fv = sigm(acc[mt][2 * q][rr * 2 + 1] + bb[q][1]);
                float gv = tanh_fast(acc[mt][2 * q + 1][rr * 2 + 0] + bb[q][2]);
                float ov = sigm(acc[mt][2 * q + 1][rr * 2 + 1] + bb[q][3]);
                float co = Cs[row * LDA + hq[q]];
                float cn = fv * co + iv * gv;
                float hn = to_tf32(ov * tanh_fast(cn));
                Cs[row * LDA + hq[q]] = cn;
                Hs[row * LDA + hq[q]] = hn;
            }
    __syncthreads();

    // --- coalesced write-out (state; plus final output on last step) ---
    float* hg = g_h[layer][(t + 1) & 1] + (size_t)rowbase * HH + hb;
    float* cg = g_c[layer] + (size_t)rowbase * HH + hb;
    const size_t NH = (size_t)NB * HH;
    float* oh = out + (size_t)layer * NH + (size_t)rowbase * HH + hb;
    float* oc = out + (size_t)(2 + layer) * NH + (size_t)rowbase * HH + hb;
    const bool last = (t == TT - 1);

    #pragma unroll
    for (int j = 0; j < 4; j++) {
        int idx = tid + j * 256;
        int row = idx >> 3, ch = idx & 7;
        float4 hv = *(const float4*)&Hs[row * LDA + ch * 4];
        float4 cv = *(const float4*)&Cs[row * LDA + ch * 4];
        *(float4*)(hg + (size_t)row * HH + ch * 4) = hv;
        *(float4*)(cg + (size_t)row * HH + ch * 4) = cv;
        if (last) {
            *(float4*)(oh + (size_t)row * HH + ch * 4) = hv;
            *(float4*)(oc + (size_t)row * HH + ch * 4) = cv;
        }
    }
}

// ---------------------------------------------------------------------------
extern "C" void kernel_launch(void* const* d_in, const int* in_sizes, int n_in,
                              void* d_out, int out_size) {
    const float* x       = (const float*)d_in[0];
    const float* coords  = (const float*)d_in[1];
    const float* env     = (const float*)d_in[2];
    const float* areas   = (const float*)d_in[3];
    const float* bird_uv = (const float*)d_in[4];
    const float* W_in    = (const float*)d_in[5];
    const float* W_ih    = (const float*)d_in[6];
    const float* W_hh    = (const float*)d_in[7];
    const float* b_ih    = (const float*)d_in[8];
    const float* b_hh    = (const float*)d_in[9];
    (void)in_sizes; (void)n_in; (void)out_size;

    cudaFuncSetAttribute(lstm_step_mma,
                         cudaFuncAttributeMaxDynamicSharedMemorySize, SMEM_DYN);

    zero_kernel<<<1024, 256>>>();
    prep_feats<<<4096, 256>>>(x, coords, env, areas, bird_uv);
    prep_weights<<<768, 256>>>(W_ih, W_hh, b_ih, b_hh);
    prep_wc<<<128, 256>>>(W_in, W_ih);

    dim3 grid(NB / BM, FOURH / BN, 2);   // (64, 8, 2) wavefront over layers
    for (int k = 0; k <= TT; k++)
        lstm_step_mma<<<grid, 256, SMEM_DYN>>>(k, (float*)d_out);
}

// round 10
// speedup vs baseline: 9.4657x; 1.4493x over previous
#include <cuda_runtime.h>
#include <cuda_fp16.h>
#include <cstdint>
#include <math.h>

// Problem constants
#define NB    8192
#define TT    48
#define HH    256
#define NENV  10
#define FOURH 1024
#define KPADH 32            // padded feature K (halfs)

// MMA tile config: CTA 128x128, 8 warps (2x4), warp tile 64x32, m16n8k16 fp16
#define BM    128
#define BN    128
#define KT    32            // k (halfs) per stage
#define LDAH  20            // 32-bit words per A/B smem row (16 data + 4 pad)
#define LDC   36            // float stride for C/H staging
#define A_WORDS_H   (BM * LDAH)          // 2560 words
#define STAGE_WORDS (2 * A_WORDS_H)      // 5120 words (A+B)
#define STAGE_BYTES (STAGE_WORDS * 4)    // 20480 B
#define CS_WORDS    (BM * LDC)           // 4608 words
#define SMEM_DYN (3 * STAGE_BYTES + CS_WORDS * 4)   // 79872 B

// ---------------------------------------------------------------------------
// Scratch
// ---------------------------------------------------------------------------
__device__ __align__(256) __half g_hH[2][2][NB * HH];   // [layer][pp][n][h]
__device__ __align__(256) float  g_c[2][NB * HH];       // [layer][n][h] fp32
__device__ __align__(256) __half g_featsH[TT * NB * KPADH];
__device__ __align__(256) __half g_WhhH[2][FOURH * HH]; // [r_perm][k]
__device__ __align__(256) __half g_Wih1H[FOURH * HH];
__device__ __align__(256) __half g_WcH[FOURH * KPADH];  // folded W_ih0 @ W_in
__device__ __align__(256) float  g_bias[2][FOURH];      // original layout g*256+h

__device__ __forceinline__ float sigm(float v) {
    return 1.0f / (1.0f + __expf(-v));
}
__device__ __forceinline__ float tanh_fast(float v) {
    return 2.0f / (1.0f + __expf(-2.0f * v)) - 1.0f;
}
__device__ __forceinline__ uint32_t smem_u32(const void* p) {
    return (uint32_t)__cvta_generic_to_shared(p);
}

// Column permutation sigma: permuted gate-row r -> original row (gate*256 + h)
__device__ __forceinline__ int sigma_orig(int r) {
    int blk = r >> 7;
    int c = r & 127;
    int h = blk * 32 + ((c >> 4) << 2) + ((c >> 1) & 3);
    int gate = (((c >> 3) & 1) << 1) | (c & 1);
    return gate * HH + h;
}

// ---------------------------------------------------------------------------
// Prep 1: feats -> half [t][n][32] (pad 0), zero h (slot 0) and c
// ---------------------------------------------------------------------------
__global__ void prep_data(const float* __restrict__ x,
                          const float* __restrict__ coords,
                          const float* __restrict__ env,
                          const float* __restrict__ areas,
                          const float* __restrict__ bird_uv) {
    const int S1 = TT * NB * KPADH;          // feats
    const int S2 = 2 * NB * HH;              // h zero (both layers, slot 0)
    const int tot = S1 + S2 + S2;            // + c zero
    for (int idx = blockIdx.x * blockDim.x + threadIdx.x; idx < tot;
         idx += gridDim.x * blockDim.x) {
        if (idx < S1) {
            int f = idx & 31;
            int n = (idx >> 5) & (NB - 1);
            int t = idx >> 18;
            float v = 0.0f;
            if (f == 0)       v = x[(size_t)n * TT + t];
            else if (f <= 2)  v = coords[n * 2 + (f - 1)];
            else if (f <= 12) v = env[((size_t)n * NENV + (f - 3)) * TT + t];
            else if (f == 13) v = areas[n];
            else if (f <= 15) v = bird_uv[((size_t)n * 2 + (f - 14)) * TT + t];
            g_featsH[idx] = __float2half_rn(v);
        } else if (idx < S1 + S2) {
            int j = idx - S1;
            int l = j / (NB * HH);
            g_hH[l][0][j - l * NB * HH] = __float2half_rn(0.0f);
        } else {
            int j = idx - S1 - S2;
            int l = j / (NB * HH);
            g_c[l][j - l * NB * HH] = 0.0f;
        }
    }
}

// ---------------------------------------------------------------------------
// Prep 2: weights (sigma-permuted rows, half), biases, folded Wc
// ---------------------------------------------------------------------------
__global__ void prep_wts(const float* __restrict__ W_in,
                         const float* __restrict__ W_ih,
                         const float* __restrict__ W_hh,
                         const float* __restrict__ b_ih,
                         const float* __restrict__ b_hh) {
    const int T1 = 524288;                 // Whh both layers
    const int T2 = T1 + 262144;            // Wih1
    const int T3 = T2 + 2048;              // biases
    const int tot = T3 + FOURH * KPADH;    // + Wc fold
    for (int i = blockIdx.x * blockDim.x + threadIdx.x; i < tot;
         i += gridDim.x * blockDim.x) {
        if (i < T1) {
            int l = i >> 18;
            int rem = i & 262143;
            int r = rem >> 8;
            int k = rem & 255;
            g_WhhH[l][rem] =
                __float2half_rn(W_hh[l * 262144 + sigma_orig(r) * HH + k]);
        } else if (i < T2) {
            int rem = i - T1;
            int r = rem >> 8;
            int k = rem & 255;
            g_Wih1H[rem] =
                __float2half_rn(W_ih[262144 + sigma_orig(r) * HH + k]);
        } else if (i < T3) {
            int j = i - T2;
            int l = j >> 10;
            int s = j & 1023;
            g_bias[l][s] = b_ih[l * FOURH + s] + b_hh[l * FOURH + s];
        } else {
            int j = i - T3;
            int k = j & 31;
            int r = j >> 5;
            float out = 0.0f;
            if (k < 16) {
                const float* wr = W_ih + sigma_orig(r) * HH;   // layer 0
                float acc = 0.0f;
                #pragma unroll 8
                for (int m = 0; m < HH; m++)
                    acc = fmaf(wr[m], W_in[m * 16 + k], acc);
                out = acc;
            }
            g_WcH[j] = __float2half_rn(out);
        }
    }
}

// ---------------------------------------------------------------------------
// Fused mma.sync fp16 LSTM wavefront step:
//   blockIdx.z = 0 -> layer 0 at t = k;  z = 1 -> layer 1 at t = k-1
// ---------------------------------------------------------------------------
__device__ __forceinline__ void issue_tile(const __half* __restrict__ Ab, int as,
                                           const __half* __restrict__ Bb, int bs,
                                           int k0, uint32_t smb, int st,
                                           int rowbase, int gbase, int tid) {
    uint32_t stA = smb + st * STAGE_BYTES;
    uint32_t stB = stA + A_WORDS_H * 4;
    #pragma unroll
    for (int jj = 0; jj < 2; jj++) {
        int idx = tid + jj * 256;
        int row = idx >> 2, ch = idx & 3;       // 4 chunks of 8 halfs per row
        const __half* srca = Ab + (size_t)(rowbase + row) * as + k0 + ch * 8;
        const __half* srcb = Bb + (size_t)(gbase + row) * bs + k0 + ch * 8;
        uint32_t da = stA + (row * LDAH + ch * 4) * 4;
        uint32_t db = stB + (row * LDAH + ch * 4) * 4;
        asm volatile(
            "cp.async.cg.shared.global [%0], [%1], 16;\n"
            "cp.async.cg.shared.global [%2], [%3], 16;\n"
            :: "r"(da), "l"(srca), "r"(db), "l"(srcb));
    }
    asm volatile("cp.async.commit_group;");
}

__device__ __forceinline__ void mma_f16(float* d, const uint32_t* a,
                                        const uint32_t* b) {
    asm volatile(
        "mma.sync.aligned.m16n8k16.row.col.f32.f16.f16.f32 "
        "{%0,%1,%2,%3}, {%4,%5,%6,%7}, {%8,%9}, {%0,%1,%2,%3};"
        : "+f"(d[0]), "+f"(d[1]), "+f"(d[2]), "+f"(d[3])
        : "r"(a[0]), "r"(a[1]), "r"(a[2]), "r"(a[3]), "r"(b[0]), "r"(b[1]));
}

__global__ __launch_bounds__(256, 2) void lstm_step_mma(int kstep,
                                                        float* __restrict__ out) {
    const int layer = blockIdx.z;
    const int t = (layer == 0) ? kstep : kstep - 1;
    if (t < 0 || t >= TT) return;

    extern __shared__ __align__(16) char dynC[];
    const uint32_t smb = smem_u32(dynC);
    float* Cs = (float*)(dynC + 3 * STAGE_BYTES);

    const int tid = threadIdx.x;
    const int wid = tid >> 5;
    const int lane = tid & 31;
    const int gid = lane >> 2;
    const int tig = lane & 3;
    const int wm = (wid & 1) * 64;
    const int wn = (wid >> 1) * 32;
    const int rowbase = blockIdx.x * BM;
    const int gbase = blockIdx.y * BN;
    const int hb = blockIdx.y * 32;

    // --- prefetch old c tile (fp32) as first cp.async group ---
    {
        const float* cg = g_c[layer] + (size_t)rowbase * HH + hb;
        #pragma unroll
        for (int j = 0; j < 4; j++) {
            int idx = tid + j * 256;
            int row = idx >> 3, ch = idx & 7;
            const float* src = cg + (size_t)row * HH + ch * 4;
            uint32_t d = smem_u32(Cs + row * LDC + ch * 4);
            asm volatile("cp.async.cg.shared.global [%0], [%1], 16;"
                         :: "r"(d), "l"(src));
        }
        asm volatile("cp.async.commit_group;");
    }

    // --- operand selection (all halfs) ---
    const __half *A0, *B0, *A1, *B1;
    int a0s, b0s, K0T;
    if (layer == 0) {
        A0 = g_featsH + (size_t)t * NB * KPADH;  a0s = KPADH;
        B0 = g_WcH;                               b0s = KPADH;
        K0T = 1;
        A1 = g_hH[0][t & 1];
        B1 = g_WhhH[0];
    } else {
        A0 = g_hH[0][(t + 1) & 1];                a0s = HH;
        B0 = g_Wih1H;                             b0s = HH;
        K0T = HH / KT;                            // 8
        A1 = g_hH[1][t & 1];
        B1 = g_WhhH[1];
    }
    const int TK = K0T + HH / KT;

    float acc[4][4][4];
    #pragma unroll
    for (int i = 0; i < 4; i++)
        #pragma unroll
        for (int j = 0; j < 4; j++)
            #pragma unroll
            for (int k = 0; k < 4; k++) acc[i][j][k] = 0.0f;

    // prologue: stages 0 and 1
    issue_tile(A0, a0s, B0, b0s, 0, smb, 0, rowbase, gbase, tid);
    {
        const __half* Ab = (1 < K0T) ? A0 : A1;
        const __half* Bb = (1 < K0T) ? B0 : B1;
        int as = (1 < K0T) ? a0s : HH;
        int bs = (1 < K0T) ? b0s : HH;
        int k0 = (1 < K0T) ? KT : 0;
        issue_tile(Ab, as, Bb, bs, k0, smb, 1, rowbase, gbase, tid);
    }

    int rd = 0;                 // stage being read (kt % 3)
    int wr = 2;                 // stage to fill next ((kt+2) % 3)
    for (int kt = 0; kt < TK; kt++) {
        if (kt == TK - 1) asm volatile("cp.async.wait_group 0;");
        else              asm volatile("cp.async.wait_group 1;");
        __syncthreads();        // all warps done reading stage (kt-1)%3 == wr

        if (kt + 2 < TK) {
            int j = kt + 2;
            const __half *Ab, *Bb;
            int as, bs, k0;
            if (j < K0T) { Ab = A0; Bb = B0; as = a0s; bs = b0s; k0 = j * KT; }
            else         { Ab = A1; Bb = B1; as = HH;  bs = HH;  k0 = (j - K0T) * KT; }
            issue_tile(Ab, as, Bb, bs, k0, smb, wr, rowbase, gbase, tid);
        }

        const uint32_t* Asu = (const uint32_t*)(dynC + rd * STAGE_BYTES);
        const uint32_t* Bsu = Asu + A_WORDS_H;

        #pragma unroll
        for (int kk = 0; kk < 2; kk++) {
            const int kb = kk * 8;
            uint32_t a[4][4];
            #pragma unroll
            for (int mt = 0; mt < 4; mt++) {
                int r0 = (wm + mt * 16 + gid) * LDAH + kb + tig;
                a[mt][0] = Asu[r0];
                a[mt][1] = Asu[r0 + 8 * LDAH];
                a[mt][2] = Asu[r0 + 4];
                a[mt][3] = Asu[r0 + 8 * LDAH + 4];
            }
            uint32_t b[4][2];
            #pragma unroll
            for (int nt = 0; nt < 4; nt++) {
                int c0 = (wn + nt * 8 + gid) * LDAH + kb + tig;
                b[nt][0] = Bsu[c0];
                b[nt][1] = Bsu[c0 + 4];
            }
            #pragma unroll
            for (int mt = 0; mt < 4; mt++)
                #pragma unroll
                for (int nt = 0; nt < 4; nt++)
                    mma_f16(acc[mt][nt], a[mt], b[nt]);
        }

        rd++; if (rd == 3) rd = 0;
        wr++; if (wr == 3) wr = 0;
    }
    __syncthreads();   // safe to reuse stage 0 as H staging

    // --- LSTM cell epilogue (fp32) ---
    float* Hs = (float*)dynC;   // alias stage 0 (5120 words >= 4608)
    int hq[2];
    float bb[2][4];
    #pragma unroll
    for (int q = 0; q < 2; q++) {
        int hl = ((wid >> 1) * 2 + q) * 4 + tig;
        hq[q] = hl;
        #pragma unroll
        for (int g = 0; g < 4; g++)
            bb[q][g] = g_bias[layer][g * HH + hb + hl];
    }

    #pragma unroll
    for (int mt = 0; mt < 4; mt++)
        #pragma unroll
        for (int q = 0; q < 2; q++)
            #pragma unroll
            for (int rr = 0; rr < 2; rr++) {
                int row = wm + mt * 16 + gid + rr * 8;
                float iv = sigm(acc[mt][2 * q][rr * 2 + 0] + bb[q][0]);
                float fv = sigm(acc[mt][2 * q][rr * 2 + 1] + bb[q][1]);
                float gv = tanh_fast(acc[mt][2 * q + 1][rr * 2 + 0] + bb[q][2]);
                float ov = sigm(acc[mt][2 * q + 1][rr * 2 + 1] + bb[q][3]);
                float co = Cs[row * LDC + hq[q]];
                float cn = fv * co + iv * gv;
                float hn = ov * tanh_fast(cn);
                Cs[row * LDC + hq[q]] = cn;
                Hs[row * LDC + hq[q]] = hn;
            }
    __syncthreads();

    // --- coalesced write-out: half state + fp32 final output ---
    __half* hgH = g_hH[layer][(t + 1) & 1] + (size_t)rowbase * HH + hb;
    float* cg = g_c[layer] + (size_t)rowbase * HH + hb;
    const size_t NH = (size_t)NB * HH;
    float* oh = out + (size_t)layer * NH + (size_t)rowbase * HH + hb;
    float* oc = out + (size_t)(2 + layer) * NH + (size_t)rowbase * HH + hb;
    const bool last = (t == TT - 1);

    #pragma unroll
    for (int j = 0; j < 4; j++) {
        int idx = tid + j * 256;
        int row = idx >> 3, ch = idx & 7;
        float4 hv = *(const float4*)&Hs[row * LDC + ch * 4];
        float4 cv = *(const float4*)&Cs[row * LDC + ch * 4];
        *(float4*)(cg + (size_t)row * HH + ch * 4) = cv;
        __half2 p0 = __floats2half2_rn(hv.x, hv.y);
        __half2 p1 = __floats2half2_rn(hv.z, hv.w);
        __half2* hd = (__half2*)(hgH + (size_t)row * HH + ch * 4);
        hd[0] = p0;
        hd[1] = p1;
        if (last) {
            *(float4*)(oh + (size_t)row * HH + ch * 4) = hv;
            *(float4*)(oc + (size_t)row * HH + ch * 4) = cv;
        }
    }
}

// ---------------------------------------------------------------------------
extern "C" void kernel_launch(void* const* d_in, const int* in_sizes, int n_in,
                              void* d_out, int out_size) {
    const float* x       = (const float*)d_in[0];
    const float* coords  = (const float*)d_in[1];
    const float* env     = (const float*)d_in[2];
    const float* areas   = (const float*)d_in[3];
    const float* bird_uv = (const float*)d_in[4];
    const float* W_in    = (const float*)d_in[5];
    const float* W_ih    = (const float*)d_in[6];
    const float* W_hh    = (const float*)d_in[7];
    const float* b_ih    = (const float*)d_in[8];
    const float* b_hh    = (const float*)d_in[9];
    (void)in_sizes; (void)n_in; (void)out_size;

    cudaFuncSetAttribute(lstm_step_mma,
                         cudaFuncAttributeMaxDynamicSharedMemorySize, SMEM_DYN);

    prep_data<<<4096, 256>>>(x, coords, env, areas, bird_uv);
    prep_wts<<<832, 256>>>(W_in, W_ih, W_hh, b_ih, b_hh);

    dim3 grid(NB / BM, FOURH / BN, 2);   // (64, 8, 2) wavefront over layers
    for (int k = 0; k <= TT; k++)
        lstm_step_mma<<<grid, 256, SMEM_DYN>>>(k, (float*)d_out);
}

// round 11
// speedup vs baseline: 9.9844x; 1.0548x over previous
#include <cuda_runtime.h>
#include <cuda_fp16.h>
#include <cstdint>
#include <math.h>

// Problem constants
#define NB    8192
#define TT    48
#define HH    256
#define NENV  10
#define FOURH 1024
#define KPADH 32            // padded feature K (halfs)

// MMA tile config: CTA 128x128, 8 warps (2x4), warp tile 64x32, m16n8k16 fp16
#define BM    128
#define BN    128
#define KT    32            // k (halfs) per stage
#define LDAH  20            // 32-bit words per A/B smem row (16 data + 4 pad)
#define LDC   36            // float stride for C/H staging
#define A_WORDS_H   (BM * LDAH)          // 2560 words
#define STAGE_WORDS (2 * A_WORDS_H)      // 5120 words (A+B)
#define STAGE_BYTES (STAGE_WORDS * 4)    // 20480 B
#define CS_WORDS    (BM * LDC)           // 4608 words
#define SMEM_DYN (3 * STAGE_BYTES + CS_WORDS * 4)   // 79872 B

// ---------------------------------------------------------------------------
// Scratch
// ---------------------------------------------------------------------------
__device__ __align__(256) __half g_hH[2][2][NB * HH];   // [layer][pp][n][h]
__device__ __align__(256) float  g_c[2][NB * HH];       // [layer][n][h] fp32
__device__ __align__(256) __half g_featsH[TT * NB * KPADH];
__device__ __align__(256) __half g_WhhH[2][FOURH * HH]; // [r_perm][k]
__device__ __align__(256) __half g_Wih1H[FOURH * HH];
__device__ __align__(256) __half g_WcH[FOURH * KPADH];  // folded W_ih0 @ W_in
__device__ __align__(256) float  g_bias[2][FOURH];      // original layout g*256+h

__device__ __forceinline__ float sigm(float v) {
    return 1.0f / (1.0f + __expf(-v));
}
__device__ __forceinline__ float tanh_fast(float v) {
    return 2.0f / (1.0f + __expf(-2.0f * v)) - 1.0f;
}
__device__ __forceinline__ uint32_t smem_u32(const void* p) {
    return (uint32_t)__cvta_generic_to_shared(p);
}

// Column permutation sigma: permuted gate-row r -> original row (gate*256 + h)
__device__ __forceinline__ int sigma_orig(int r) {
    int blk = r >> 7;
    int c = r & 127;
    int h = blk * 32 + ((c >> 4) << 2) + ((c >> 1) & 3);
    int gate = (((c >> 3) & 1) << 1) | (c & 1);
    return gate * HH + h;
}

// ---------------------------------------------------------------------------
// Prep 1: feats -> half [t][n][32] (pad 0), zero h (slot 0) and c
// ---------------------------------------------------------------------------
__global__ void prep_data(const float* __restrict__ x,
                          const float* __restrict__ coords,
                          const float* __restrict__ env,
                          const float* __restrict__ areas,
                          const float* __restrict__ bird_uv) {
    const int S1 = TT * NB * KPADH;
    const int S2 = 2 * NB * HH;
    const int tot = S1 + S2 + S2;
    for (int idx = blockIdx.x * blockDim.x + threadIdx.x; idx < tot;
         idx += gridDim.x * blockDim.x) {
        if (idx < S1) {
            int f = idx & 31;
            int n = (idx >> 5) & (NB - 1);
            int t = idx >> 18;
            float v = 0.0f;
            if (f == 0)       v = x[(size_t)n * TT + t];
            else if (f <= 2)  v = coords[n * 2 + (f - 1)];
            else if (f <= 12) v = env[((size_t)n * NENV + (f - 3)) * TT + t];
            else if (f == 13) v = areas[n];
            else if (f <= 15) v = bird_uv[((size_t)n * 2 + (f - 14)) * TT + t];
            g_featsH[idx] = __float2half_rn(v);
        } else if (idx < S1 + S2) {
            int j = idx - S1;
            int l = j / (NB * HH);
            g_hH[l][0][j - l * NB * HH] = __float2half_rn(0.0f);
        } else {
            int j = idx - S1 - S2;
            int l = j / (NB * HH);
            g_c[l][j - l * NB * HH] = 0.0f;
        }
    }
}

// ---------------------------------------------------------------------------
// Prep 2: weights (sigma-permuted rows, half), biases, folded Wc
// ---------------------------------------------------------------------------
__global__ void prep_wts(const float* __restrict__ W_in,
                         const float* __restrict__ W_ih,
                         const float* __restrict__ W_hh,
                         const float* __restrict__ b_ih,
                         const float* __restrict__ b_hh) {
    const int T1 = 524288;
    const int T2 = T1 + 262144;
    const int T3 = T2 + 2048;
    const int tot = T3 + FOURH * KPADH;
    for (int i = blockIdx.x * blockDim.x + threadIdx.x; i < tot;
         i += gridDim.x * blockDim.x) {
        if (i < T1) {
            int l = i >> 18;
            int rem = i & 262143;
            int r = rem >> 8;
            int k = rem & 255;
            g_WhhH[l][rem] =
                __float2half_rn(W_hh[l * 262144 + sigma_orig(r) * HH + k]);
        } else if (i < T2) {
            int rem = i - T1;
            int r = rem >> 8;
            int k = rem & 255;
            g_Wih1H[rem] =
                __float2half_rn(W_ih[262144 + sigma_orig(r) * HH + k]);
        } else if (i < T3) {
            int j = i - T2;
            int l = j >> 10;
            int s = j & 1023;
            g_bias[l][s] = b_ih[l * FOURH + s] + b_hh[l * FOURH + s];
        } else {
            int j = i - T3;
            int k = j & 31;
            int r = j >> 5;
            float out = 0.0f;
            if (k < 16) {
                const float* wr = W_ih + sigma_orig(r) * HH;   // layer 0
                float acc = 0.0f;
                #pragma unroll 8
                for (int m = 0; m < HH; m++)
                    acc = fmaf(wr[m], W_in[m * 16 + k], acc);
                out = acc;
            }
            g_WcH[j] = __float2half_rn(out);
        }
    }
}

// ---------------------------------------------------------------------------
// Fused mma.sync fp16 LSTM wavefront step (ldmatrix fragment loads)
// ---------------------------------------------------------------------------
__device__ __forceinline__ void issue_tile(const __half* __restrict__ Ab, int as,
                                           const __half* __restrict__ Bb, int bs,
                                           int k0, uint32_t smb, int st,
                                           int rowbase, int gbase, int tid) {
    uint32_t stA = smb + st * STAGE_BYTES;
    uint32_t stB = stA + A_WORDS_H * 4;
    #pragma unroll
    for (int jj = 0; jj < 2; jj++) {
        int idx = tid + jj * 256;
        int row = idx >> 2, ch = idx & 3;
        const __half* srca = Ab + (size_t)(rowbase + row) * as + k0 + ch * 8;
        const __half* srcb = Bb + (size_t)(gbase + row) * bs + k0 + ch * 8;
        uint32_t da = stA + (row * LDAH + ch * 4) * 4;
        uint32_t db = stB + (row * LDAH + ch * 4) * 4;
        asm volatile(
            "cp.async.cg.shared.global [%0], [%1], 16;\n"
            "cp.async.cg.shared.global [%2], [%3], 16;\n"
            :: "r"(da), "l"(srca), "r"(db), "l"(srcb));
    }
    asm volatile("cp.async.commit_group;");
}

__device__ __forceinline__ void mma_f16(float* d, const uint32_t* a,
                                        const uint32_t* b) {
    asm volatile(
        "mma.sync.aligned.m16n8k16.row.col.f32.f16.f16.f32 "
        "{%0,%1,%2,%3}, {%4,%5,%6,%7}, {%8,%9}, {%0,%1,%2,%3};"
        : "+f"(d[0]), "+f"(d[1]), "+f"(d[2]), "+f"(d[3])
        : "r"(a[0]), "r"(a[1]), "r"(a[2]), "r"(a[3]), "r"(b[0]), "r"(b[1]));
}

__device__ __forceinline__ void ldm_x4(uint32_t* r, uint32_t addr) {
    asm volatile(
        "ldmatrix.sync.aligned.m8n8.x4.shared.b16 {%0,%1,%2,%3}, [%4];"
        : "=r"(r[0]), "=r"(r[1]), "=r"(r[2]), "=r"(r[3]) : "r"(addr));
}

__global__ __launch_bounds__(256, 2) void lstm_step_mma(int kstep,
                                                        float* __restrict__ out) {
    const int layer = blockIdx.z;
    const int t = (layer == 0) ? kstep : kstep - 1;
    if (t < 0 || t >= TT) return;

    extern __shared__ __align__(16) char dynC[];
    const uint32_t smb = smem_u32(dynC);
    float* Cs = (float*)(dynC + 3 * STAGE_BYTES);

    const int tid = threadIdx.x;
    const int wid = tid >> 5;
    const int lane = tid & 31;
    const int gid = lane >> 2;
    const int tig = lane & 3;
    const int wm = (wid & 1) * 64;
    const int wn = (wid >> 1) * 32;
    const int rowbase = blockIdx.x * BM;
    const int gbase = blockIdx.y * BN;
    const int hb = blockIdx.y * 32;

    // ldmatrix lane-invariant address offsets (in bytes, within a stage)
    // A: row = wm + ((lane>>3)&1)*8 + (lane&7), 16B-chunk = (lane>>4)
    // B: row = wn + ((lane>>4)&1)*8 + (lane&7), 16B-chunk = ((lane>>3)&1)
    const uint32_t a_off =
        ((uint32_t)((wm + ((lane >> 3) & 1) * 8 + (lane & 7)) * LDAH +
                    (lane >> 4) * 4)) << 2;
    const uint32_t b_off =
        ((uint32_t)((wn + ((lane >> 4) & 1) * 8 + (lane & 7)) * LDAH +
                    ((lane >> 3) & 1) * 4) + A_WORDS_H) << 2;

    // --- prefetch old c tile (fp32) as first cp.async group ---
    {
        const float* cg = g_c[layer] + (size_t)rowbase * HH + hb;
        #pragma unroll
        for (int j = 0; j < 4; j++) {
            int idx = tid + j * 256;
            int row = idx >> 3, ch = idx & 7;
            const float* src = cg + (size_t)row * HH + ch * 4;
            uint32_t d = smem_u32(Cs + row * LDC + ch * 4);
            asm volatile("cp.async.cg.shared.global [%0], [%1], 16;"
                         :: "r"(d), "l"(src));
        }
        asm volatile("cp.async.commit_group;");
    }

    // --- operand selection ---
    const __half *A0, *B0, *A1, *B1;
    int a0s, b0s, K0T;
    if (layer == 0) {
        A0 = g_featsH + (size_t)t * NB * KPADH;  a0s = KPADH;
        B0 = g_WcH;                               b0s = KPADH;
        K0T = 1;
        A1 = g_hH[0][t & 1];
        B1 = g_WhhH[0];
    } else {
        A0 = g_hH[0][(t + 1) & 1];                a0s = HH;
        B0 = g_Wih1H;                             b0s = HH;
        K0T = HH / KT;                            // 8
        A1 = g_hH[1][t & 1];
        B1 = g_WhhH[1];
    }
    const int TK = K0T + HH / KT;

    float acc[4][4][4];
    #pragma unroll
    for (int i = 0; i < 4; i++)
        #pragma unroll
        for (int j = 0; j < 4; j++)
            #pragma unroll
            for (int k = 0; k < 4; k++) acc[i][j][k] = 0.0f;

    // prologue: stages 0 and 1
    issue_tile(A0, a0s, B0, b0s, 0, smb, 0, rowbase, gbase, tid);
    {
        const __half* Ab = (1 < K0T) ? A0 : A1;
        const __half* Bb = (1 < K0T) ? B0 : B1;
        int as = (1 < K0T) ? a0s : HH;
        int bs = (1 < K0T) ? b0s : HH;
        int k0 = (1 < K0T) ? KT : 0;
        issue_tile(Ab, as, Bb, bs, k0, smb, 1, rowbase, gbase, tid);
    }

    int rd = 0, wr = 2;
    for (int kt = 0; kt < TK; kt++) {
        if (kt == TK - 1) asm volatile("cp.async.wait_group 0;");
        else              asm volatile("cp.async.wait_group 1;");
        __syncthreads();

        if (kt + 2 < TK) {
            int j = kt + 2;
            const __half *Ab, *Bb;
            int as, bs, k0;
            if (j < K0T) { Ab = A0; Bb = B0; as = a0s; bs = b0s; k0 = j * KT; }
            else         { Ab = A1; Bb = B1; as = HH;  bs = HH;  k0 = (j - K0T) * KT; }
            issue_tile(Ab, as, Bb, bs, k0, smb, wr, rowbase, gbase, tid);
        }

        const uint32_t stage = smb + rd * STAGE_BYTES;
        const uint32_t aB = stage + a_off;
        const uint32_t bB = stage + b_off;

        #pragma unroll
        for (int kk = 0; kk < 2; kk++) {
            const uint32_t kbb = (uint32_t)(kk * 8) << 2;   // k-chunk byte offset
            uint32_t a[4][4];
            #pragma unroll
            for (int mt = 0; mt < 4; mt++)
                ldm_x4(a[mt], aB + ((uint32_t)(mt * 16 * LDAH) << 2) + kbb);
            uint32_t b[2][4];
            #pragma unroll
            for (int p = 0; p < 2; p++)
                ldm_x4(b[p], bB + ((uint32_t)(p * 16 * LDAH) << 2) + kbb);
            #pragma unroll
            for (int mt = 0; mt < 4; mt++)
                #pragma unroll
                for (int nt = 0; nt < 4; nt++)
                    mma_f16(acc[mt][nt], a[mt], &b[nt >> 1][(nt & 1) * 2]);
        }

        rd++; if (rd == 3) rd = 0;
        wr++; if (wr == 3) wr = 0;
    }
    __syncthreads();   // safe to reuse stage 0 as H staging

    // --- LSTM cell epilogue (fp32) ---
    float* Hs = (float*)dynC;   // alias stage 0
    int hq[2];
    float bb[2][4];
    #pragma unroll
    for (int q = 0; q < 2; q++) {
        int hl = ((wid >> 1) * 2 + q) * 4 + tig;
        hq[q] = hl;
        #pragma unroll
        for (int g = 0; g < 4; g++)
            bb[q][g] = g_bias[layer][g * HH + hb + hl];
    }

    #pragma unroll
    for (int mt = 0; mt < 4; mt++)
        #pragma unroll
        for (int q = 0; q < 2; q++)
            #pragma unroll
            for (int rr = 0; rr < 2; rr++) {
                int row = wm + mt * 16 + gid + rr * 8;
                float iv = sigm(acc[mt][2 * q][rr * 2 + 0] + bb[q][0]);
                float fv = sigm(acc[mt][2 * q][rr * 2 + 1] + bb[q][1]);
                float gv = tanh_fast(acc[mt][2 * q + 1][rr * 2 + 0] + bb[q][2]);
                float ov = sigm(acc[mt][2 * q + 1][rr * 2 + 1] + bb[q][3]);
                float co = Cs[row * LDC + hq[q]];
                float cn = fv * co + iv * gv;
                float hn = ov * tanh_fast(cn);
                Cs[row * LDC + hq[q]] = cn;
                Hs[row * LDC + hq[q]] = hn;
            }
    __syncthreads();

    // --- coalesced write-out: half state + fp32 final output ---
    __half* hgH = g_hH[layer][(t + 1) & 1] + (size_t)rowbase * HH + hb;
    float* cg = g_c[layer] + (size_t)rowbase * HH + hb;
    const size_t NH = (size_t)NB * HH;
    float* oh = out + (size_t)layer * NH + (size_t)rowbase * HH + hb;
    float* oc = out + (size_t)(2 + layer) * NH + (size_t)rowbase * HH + hb;
    const bool last = (t == TT - 1);

    #pragma unroll
    for (int j = 0; j < 4; j++) {
        int idx = tid + j * 256;
        int row = idx >> 3, ch = idx & 7;
        float4 hv = *(const float4*)&Hs[row * LDC + ch * 4];
        float4 cv = *(const float4*)&Cs[row * LDC + ch * 4];
        *(float4*)(cg + (size_t)row * HH + ch * 4) = cv;
        __half2 p0 = __floats2half2_rn(hv.x, hv.y);
        __half2 p1 = __floats2half2_rn(hv.z, hv.w);
        __half2* hd = (__half2*)(hgH + (size_t)row * HH + ch * 4);
        hd[0] = p0;
        hd[1] = p1;
        if (last) {
            *(float4*)(oh + (size_t)row * HH + ch * 4) = hv;
            *(float4*)(oc + (size_t)row * HH + ch * 4) = cv;
        }
    }
}

// ---------------------------------------------------------------------------
extern "C" void kernel_launch(void* const* d_in, const int* in_sizes, int n_in,
                              void* d_out, int out_size) {
    const float* x       = (const float*)d_in[0];
    const float* coords  = (const float*)d_in[1];
    const float* env     = (const float*)d_in[2];
    const float* areas   = (const float*)d_in[3];
    const float* bird_uv = (const float*)d_in[4];
    const float* W_in    = (const float*)d_in[5];
    const float* W_ih    = (const float*)d_in[6];
    const float* W_hh    = (const float*)d_in[7];
    const float* b_ih    = (const float*)d_in[8];
    const float* b_hh    = (const float*)d_in[9];
    (void)in_sizes; (void)n_in; (void)out_size;

    cudaFuncSetAttribute(lstm_step_mma,
                         cudaFuncAttributeMaxDynamicSharedMemorySize, SMEM_DYN);

    prep_data<<<4096, 256>>>(x, coords, env, areas, bird_uv);
    prep_wts<<<832, 256>>>(W_in, W_ih, W_hh, b_ih, b_hh);

    dim3 grid(NB / BM, FOURH / BN, 2);   // (64, 8, 2) wavefront over layers
    for (int k = 0; k <= TT; k++)
        lstm_step_mma<<<grid, 256, SMEM_DYN>>>(k, (float*)d_out);
}

// round 12
// speedup vs baseline: 11.4972x; 1.1515x over previous
#include <cuda_runtime.h>
#include <cuda_fp16.h>
#include <cstdint>
#include <math.h>

// Problem constants
#define NB    8192
#define TT    48
#define HH    256
#define NENV  10
#define FOURH 1024
#define KPADH 64            // padded feature K (halfs)

// MMA tile config: CTA 128x128, 8 warps (2x4), warp tile 64x32, m16n8k16 fp16
// KT=64 k per stage, swizzled 128B rows (no padding), 3 stages, 1 sync/tile.
#define BM    128
#define BN    128
#define KT    64            // k (halfs) per stage
#define ROWB  128           // bytes per A/B smem row (64 halfs)
#define A_BYTES     (BM * ROWB)          // 16384
#define STAGE_BYTES (2 * A_BYTES)        // 32768 (A+B)
#define LDC   32            // float stride for C/H staging (32 words)
#define CS_BYTES    (BM * LDC * 4)       // 16384
#define SMEM_DYN (3 * STAGE_BYTES + CS_BYTES)   // 114688 B

// ---------------------------------------------------------------------------
// Scratch
// ---------------------------------------------------------------------------
__device__ __align__(256) __half g_hH[2][2][NB * HH];   // [layer][pp][n][h]
__device__ __align__(256) float  g_c[2][NB * HH];       // [layer][n][h] fp32
__device__ __align__(256) __half g_featsH[TT * NB * KPADH];
__device__ __align__(256) __half g_WhhH[2][FOURH * HH]; // [r_perm][k]
__device__ __align__(256) __half g_Wih1H[FOURH * HH];
__device__ __align__(256) __half g_WcH[FOURH * KPADH];  // folded W_ih0 @ W_in
__device__ __align__(256) float  g_bias[2][FOURH];      // original layout g*256+h

__device__ __forceinline__ float sigm(float v) {
    return 1.0f / (1.0f + __expf(-v));
}
__device__ __forceinline__ float tanh_fast(float v) {
    return 2.0f / (1.0f + __expf(-2.0f * v)) - 1.0f;
}
__device__ __forceinline__ uint32_t smem_u32(const void* p) {
    return (uint32_t)__cvta_generic_to_shared(p);
}

// Column permutation sigma: permuted gate-row r -> original row (gate*256 + h)
__device__ __forceinline__ int sigma_orig(int r) {
    int blk = r >> 7;
    int c = r & 127;
    int h = blk * 32 + ((c >> 4) << 2) + ((c >> 1) & 3);
    int gate = (((c >> 3) & 1) << 1) | (c & 1);
    return gate * HH + h;
}

// ---------------------------------------------------------------------------
// Prep 1: feats -> half [t][n][64] (pad 0), zero h (slot 0) and c
// ---------------------------------------------------------------------------
__global__ void prep_data(const float* __restrict__ x,
                          const float* __restrict__ coords,
                          const float* __restrict__ env,
                          const float* __restrict__ areas,
                          const float* __restrict__ bird_uv) {
    const int S1 = TT * NB * KPADH;
    const int S2 = 2 * NB * HH;
    const int tot = S1 + S2 + S2;
    for (int idx = blockIdx.x * blockDim.x + threadIdx.x; idx < tot;
         idx += gridDim.x * blockDim.x) {
        if (idx < S1) {
            int f = idx & 63;
            int n = (idx >> 6) & (NB - 1);
            int t = idx >> 19;
            float v = 0.0f;
            if (f == 0)       v = x[(size_t)n * TT + t];
            else if (f <= 2)  v = coords[n * 2 + (f - 1)];
            else if (f <= 12) v = env[((size_t)n * NENV + (f - 3)) * TT + t];
            else if (f == 13) v = areas[n];
            else if (f <= 15) v = bird_uv[((size_t)n * 2 + (f - 14)) * TT + t];
            g_featsH[idx] = __float2half_rn(v);
        } else if (idx < S1 + S2) {
            int j = idx - S1;
            int l = j / (NB * HH);
            g_hH[l][0][j - l * NB * HH] = __float2half_rn(0.0f);
        } else {
            int j = idx - S1 - S2;
            int l = j / (NB * HH);
            g_c[l][j - l * NB * HH] = 0.0f;
        }
    }
}

// ---------------------------------------------------------------------------
// Prep 2: weights (sigma-permuted rows, half), biases, folded Wc (k pad 64)
// ---------------------------------------------------------------------------
__global__ void prep_wts(const float* __restrict__ W_in,
                         const float* __restrict__ W_ih,
                         const float* __restrict__ W_hh,
                         const float* __restrict__ b_ih,
                         const float* __restrict__ b_hh) {
    const int T1 = 524288;
    const int T2 = T1 + 262144;
    const int T3 = T2 + 2048;
    const int tot = T3 + FOURH * KPADH;
    for (int i = blockIdx.x * blockDim.x + threadIdx.x; i < tot;
         i += gridDim.x * blockDim.x) {
        if (i < T1) {
            int l = i >> 18;
            int rem = i & 262143;
            int r = rem >> 8;
            int k = rem & 255;
            g_WhhH[l][rem] =
                __float2half_rn(W_hh[l * 262144 + sigma_orig(r) * HH + k]);
        } else if (i < T2) {
            int rem = i - T1;
            int r = rem >> 8;
            int k = rem & 255;
            g_Wih1H[rem] =
                __float2half_rn(W_ih[262144 + sigma_orig(r) * HH + k]);
        } else if (i < T3) {
            int j = i - T2;
            int l = j >> 10;
            int s = j & 1023;
            g_bias[l][s] = b_ih[l * FOURH + s] + b_hh[l * FOURH + s];
        } else {
            int j = i - T3;
            int k = j & 63;
            int r = j >> 6;
            float out = 0.0f;
            if (k < 16) {
                const float* wr = W_ih + sigma_orig(r) * HH;   // layer 0
                float acc = 0.0f;
                #pragma unroll 8
                for (int m = 0; m < HH; m++)
                    acc = fmaf(wr[m], W_in[m * 16 + k], acc);
                out = acc;
            }
            g_WcH[j] = __float2half_rn(out);
        }
    }
}

// ---------------------------------------------------------------------------
// Fused mma.sync fp16 LSTM wavefront step (swizzled smem, KT=64)
// ---------------------------------------------------------------------------
__device__ __forceinline__ void issue_tile(const __half* __restrict__ Ab, int as,
                                           const __half* __restrict__ Bb, int bs,
                                           int k0, uint32_t smb, int st,
                                           int rowbase, int gbase, int tid) {
    uint32_t stA = smb + st * STAGE_BYTES;
    uint32_t stB = stA + A_BYTES;
    #pragma unroll
    for (int jj = 0; jj < 4; jj++) {
        int idx = tid + jj * 256;                 // 0..1023
        int row = idx >> 3, ch = idx & 7;
        int chs = ch ^ (row & 7);                 // swizzle
        const __half* srca = Ab + (size_t)(rowbase + row) * as + k0 + ch * 8;
        const __half* srcb = Bb + (size_t)(gbase + row) * bs + k0 + ch * 8;
        uint32_t da = stA + row * ROWB + chs * 16;
        uint32_t db = stB + row * ROWB + chs * 16;
        asm volatile(
            "cp.async.cg.shared.global [%0], [%1], 16;\n"
            "cp.async.cg.shared.global [%2], [%3], 16;\n"
            :: "r"(da), "l"(srca), "r"(db), "l"(srcb));
    }
    asm volatile("cp.async.commit_group;");
}

__device__ __forceinline__ void mma_f16(float* d, const uint32_t* a,
                                        const uint32_t* b) {
    asm volatile(
        "mma.sync.aligned.m16n8k16.row.col.f32.f16.f16.f32 "
        "{%0,%1,%2,%3}, {%4,%5,%6,%7}, {%8,%9}, {%0,%1,%2,%3};"
        : "+f"(d[0]), "+f"(d[1]), "+f"(d[2]), "+f"(d[3])
        : "r"(a[0]), "r"(a[1]), "r"(a[2]), "r"(a[3]), "r"(b[0]), "r"(b[1]));
}

__device__ __forceinline__ void ldm_x4(uint32_t* r, uint32_t addr) {
    asm volatile(
        "ldmatrix.sync.aligned.m8n8.x4.shared.b16 {%0,%1,%2,%3}, [%4];"
        : "=r"(r[0]), "=r"(r[1]), "=r"(r[2]), "=r"(r[3]) : "r"(addr));
}

__global__ __launch_bounds__(256, 2) void lstm_step_mma(int kstep,
                                                        float* __restrict__ out) {
    const int layer = blockIdx.z;
    const int t = (layer == 0) ? kstep : kstep - 1;
    if (t < 0 || t >= TT) return;

    extern __shared__ __align__(16) char dynC[];
    const uint32_t smb = smem_u32(dynC);
    float* Cs = (float*)(dynC + 3 * STAGE_BYTES);

    const int tid = threadIdx.x;
    const int wid = tid >> 5;
    const int lane = tid & 31;
    const int gid = lane >> 2;
    const int tig = lane & 3;
    const int wm = (wid & 1) * 64;
    const int wn = (wid >> 1) * 32;
    const int rowbase = blockIdx.x * BM;
    const int gbase = blockIdx.y * BN;
    const int hb = blockIdx.y * 32;

    // ldmatrix lane-invariant components (swizzled layout)
    const int l7 = lane & 7;
    const uint32_t aRow = (uint32_t)(wm + ((lane >> 3) & 1) * 8 + l7) * ROWB;
    const uint32_t bRow = (uint32_t)(wn + ((lane >> 4) & 1) * 8 + l7) * ROWB +
                          A_BYTES;
    const int c0a = (lane >> 4) & 1;
    const int c0b = (lane >> 3) & 1;

    // --- prefetch old c tile (fp32) as first cp.async group ---
    {
        const float* cg = g_c[layer] + (size_t)rowbase * HH + hb;
        #pragma unroll
        for (int j = 0; j < 4; j++) {
            int idx = tid + j * 256;
            int row = idx >> 3, ch = idx & 7;
            const float* src = cg + (size_t)row * HH + ch * 4;
            uint32_t d = smem_u32(Cs + row * LDC + ch * 4);
            asm volatile("cp.async.cg.shared.global [%0], [%1], 16;"
                         :: "r"(d), "l"(src));
        }
        asm volatile("cp.async.commit_group;");
    }

    // --- operand selection ---
    const __half *A0, *B0, *A1, *B1;
    int a0s, b0s, K0T;
    if (layer == 0) {
        A0 = g_featsH + (size_t)t * NB * KPADH;  a0s = KPADH;
        B0 = g_WcH;                               b0s = KPADH;
        K0T = 1;
        A1 = g_hH[0][t & 1];
        B1 = g_WhhH[0];
    } else {
        A0 = g_hH[0][(t + 1) & 1];                a0s = HH;
        B0 = g_Wih1H;                             b0s = HH;
        K0T = HH / KT;                            // 4
        A1 = g_hH[1][t & 1];
        B1 = g_WhhH[1];
    }
    const int TK = K0T + HH / KT;                 // layer0: 5, layer1: 8

    float acc[4][4][4];
    #pragma unroll
    for (int i = 0; i < 4; i++)
        #pragma unroll
        for (int j = 0; j < 4; j++)
            #pragma unroll
            for (int k = 0; k < 4; k++) acc[i][j][k] = 0.0f;

    // prologue: stages 0 and 1
    issue_tile(A0, a0s, B0, b0s, 0, smb, 0, rowbase, gbase, tid);
    {
        const __half* Ab = (1 < K0T) ? A0 : A1;
        const __half* Bb = (1 < K0T) ? B0 : B1;
        int as = (1 < K0T) ? a0s : HH;
        int bs = (1 < K0T) ? b0s : HH;
        int k0 = (1 < K0T) ? KT : 0;
        issue_tile(Ab, as, Bb, bs, k0, smb, 1, rowbase, gbase, tid);
    }

    int rd = 0, wr = 2;
    for (int kt = 0; kt < TK; kt++) {
        if (kt == TK - 1) asm volatile("cp.async.wait_group 0;");
        else              asm volatile("cp.async.wait_group 1;");
        __syncthreads();

        if (kt + 2 < TK) {
            int j = kt + 2;
            const __half *Ab, *Bb;
            int as, bs, k0;
            if (j < K0T) { Ab = A0; Bb = B0; as = a0s; bs = b0s; k0 = j * KT; }
            else         { Ab = A1; Bb = B1; as = HH;  bs = HH;  k0 = (j - K0T) * KT; }
            issue_tile(Ab, as, Bb, bs, k0, smb, wr, rowbase, gbase, tid);
        }

        const uint32_t stage = smb + rd * STAGE_BYTES;
        const uint32_t aB = stage + aRow;
        const uint32_t bB = stage + bRow;

        #pragma unroll
        for (int kk = 0; kk < 4; kk++) {
            const uint32_t chA = (uint32_t)(((kk * 2 + c0a) ^ l7) << 4);
            const uint32_t chB = (uint32_t)(((kk * 2 + c0b) ^ l7) << 4);
            uint32_t a[4][4];
            #pragma unroll
            for (int mt = 0; mt < 4; mt++)
                ldm_x4(a[mt], aB + (uint32_t)(mt * 16 * ROWB) + chA);
            uint32_t b[2][4];
            #pragma unroll
            for (int p = 0; p < 2; p++)
                ldm_x4(b[p], bB + (uint32_t)(p * 16 * ROWB) + chB);
            #pragma unroll
            for (int mt = 0; mt < 4; mt++)
                #pragma unroll
                for (int nt = 0; nt < 4; nt++)
                    mma_f16(acc[mt][nt], a[mt], &b[nt >> 1][(nt & 1) * 2]);
        }

        rd++; if (rd == 3) rd = 0;
        wr++; if (wr == 3) wr = 0;
    }
    __syncthreads();   // safe to reuse stage 0 as H staging

    // --- LSTM cell epilogue (fp32) ---
    float* Hs = (float*)dynC;   // alias stage 0 (8192 words >= 4096)
    int hq[2];
    float bb[2][4];
    #pragma unroll
    for (int q = 0; q < 2; q++) {
        int hl = ((wid >> 1) * 2 + q) * 4 + tig;
        hq[q] = hl;
        #pragma unroll
        for (int g = 0; g < 4; g++)
            bb[q][g] = g_bias[layer][g * HH + hb + hl];
    }

    #pragma unroll
    for (int mt = 0; mt < 4; mt++)
        #pragma unroll
        for (int q = 0; q < 2; q++)
            #pragma unroll
            for (int rr = 0; rr < 2; rr++) {
                int row = wm + mt * 16 + gid + rr * 8;
                float iv = sigm(acc[mt][2 * q][rr * 2 + 0] + bb[q][0]);
                float fv = sigm(acc[mt][2 * q][rr * 2 + 1] + bb[q][1]);
                float gv = tanh_fast(acc[mt][2 * q + 1][rr * 2 + 0] + bb[q][2]);
                float ov = sigm(acc[mt][2 * q + 1][rr * 2 + 1] + bb[q][3]);
                float co = Cs[row * LDC + hq[q]];
                float cn = fv * co + iv * gv;
                float hn = ov * tanh_fast(cn);
                Cs[row * LDC + hq[q]] = cn;
                Hs[row * LDC + hq[q]] = hn;
            }
    __syncthreads();

    // --- coalesced write-out: half state + fp32 final output ---
    __half* hgH = g_hH[layer][(t + 1) & 1] + (size_t)rowbase * HH + hb;
    float* cg = g_c[layer] + (size_t)rowbase * HH + hb;
    const size_t NH = (size_t)NB * HH;
    float* oh = out + (size_t)layer * NH + (size_t)rowbase * HH + hb;
    float* oc = out + (size_t)(2 + layer) * NH + (size_t)rowbase * HH + hb;
    const bool last = (t == TT - 1);

    #pragma unroll
    for (int j = 0; j < 4; j++) {
        int idx = tid + j * 256;
        int row = idx >> 3, ch = idx & 7;
        float4 hv = *(const float4*)&Hs[row * LDC + ch * 4];
        float4 cv = *(const float4*)&Cs[row * LDC + ch * 4];
        *(float4*)(cg + (size_t)row * HH + ch * 4) = cv;
        __half2 p0 = __floats2half2_rn(hv.x, hv.y);
        __half2 p1 = __floats2half2_rn(hv.z, hv.w);
        __half2* hd = (__half2*)(hgH + (size_t)row * HH + ch * 4);
        hd[0] = p0;
        hd[1] = p1;
        if (last) {
            *(float4*)(oh + (size_t)row * HH + ch * 4) = hv;
            *(float4*)(oc + (size_t)row * HH + ch * 4) = cv;
        }
    }
}

// ---------------------------------------------------------------------------
extern "C" void kernel_launch(void* const* d_in, const int* in_sizes, int n_in,
                              void* d_out, int out_size) {
    const float* x       = (const float*)d_in[0];
    const float* coords  = (const float*)d_in[1];
    const float* env     = (const float*)d_in[2];
    const float* areas   = (const float*)d_in[3];
    const float* bird_uv = (const float*)d_in[4];
    const float* W_in    = (const float*)d_in[5];
    const float* W_ih    = (const float*)d_in[6];
    const float* W_hh    = (const float*)d_in[7];
    const float* b_ih    = (const float*)d_in[8];
    const float* b_hh    = (const float*)d_in[9];
    (void)in_sizes; (void)n_in; (void)out_size;

    cudaFuncSetAttribute(lstm_step_mma,
                         cudaFuncAttributeMaxDynamicSharedMemorySize, SMEM_DYN);

    prep_data<<<8192, 256>>>(x, coords, env, areas, bird_uv);
    prep_wts<<<832, 256>>>(W_in, W_ih, W_hh, b_ih, b_hh);

    dim3 grid(NB / BM, FOURH / BN, 2);   // (64, 8, 2) wavefront over layers
    for (int k = 0; k <= TT; k++)
        lstm_step_mma<<<grid, 256, SMEM_DYN>>>(k, (float*)d_out);
}

// round 13
// speedup vs baseline: 12.2779x; 1.0679x over previous
#include <cuda_runtime.h>
#include <cuda_fp16.h>
#include <cstdint>
#include <math.h>

// Problem constants
#define NB    8192
#define TT    48
#define HH    256
#define NENV  10
#define FOURH 1024
#define KPADH 64            // padded feature K (halfs)

// MMA tile config: CTA 64x128, 8 warps (2x4), warp tile 32x32, m16n8k16 fp16
// KT=64 k per stage, swizzled 128B rows, 3 stages, 1 sync/tile, 3 CTAs/SM.
#define BM    64
#define BN    128
#define KT    64
#define ROWB  128           // bytes per A/B smem row (64 halfs)
#define A_BYTES     (BM * ROWB)              // 8192
#define B_BYTES     (BN * ROWB)              // 16384
#define STAGE_BYTES (A_BYTES + B_BYTES)      // 24576
#define LDC   36            // float stride for H/C staging
#define SMEM_DYN (3 * STAGE_BYTES)           // 73728 B

// ---------------------------------------------------------------------------
// Scratch
// ---------------------------------------------------------------------------
__device__ __align__(256) __half g_hH[2][2][NB * HH];   // [layer][pp][n][h]
__device__ __align__(256) float  g_c[2][NB * HH];       // [layer][n][h] fp32
__device__ __align__(256) __half g_featsH[TT * NB * KPADH];
__device__ __align__(256) __half g_WhhH[2][FOURH * HH]; // [r_perm][k]
__device__ __align__(256) __half g_Wih1H[FOURH * HH];
__device__ __align__(256) __half g_WcH[FOURH * KPADH];  // folded W_ih0 @ W_in
__device__ __align__(256) float  g_bias[2][FOURH];      // original layout g*256+h

__device__ __forceinline__ float sigm(float v) {
    return 1.0f / (1.0f + __expf(-v));
}
__device__ __forceinline__ float tanh_fast(float v) {
    return 2.0f / (1.0f + __expf(-2.0f * v)) - 1.0f;
}
__device__ __forceinline__ uint32_t smem_u32(const void* p) {
    return (uint32_t)__cvta_generic_to_shared(p);
}

// Column permutation sigma: permuted gate-row r -> original row (gate*256 + h)
__device__ __forceinline__ int sigma_orig(int r) {
    int blk = r >> 7;
    int c = r & 127;
    int h = blk * 32 + ((c >> 4) << 2) + ((c >> 1) & 3);
    int gate = (((c >> 3) & 1) << 1) | (c & 1);
    return gate * HH + h;
}

// ---------------------------------------------------------------------------
// Prep 1: feats -> half [t][n][64] (pad 0), zero h (slot 0) and c
// ---------------------------------------------------------------------------
__global__ void prep_data(const float* __restrict__ x,
                          const float* __restrict__ coords,
                          const float* __restrict__ env,
                          const float* __restrict__ areas,
                          const float* __restrict__ bird_uv) {
    const int S1 = TT * NB * KPADH;
    const int S2 = 2 * NB * HH;
    const int tot = S1 + S2 + S2;
    for (int idx = blockIdx.x * blockDim.x + threadIdx.x; idx < tot;
         idx += gridDim.x * blockDim.x) {
        if (idx < S1) {
            int f = idx & 63;
            int n = (idx >> 6) & (NB - 1);
            int t = idx >> 19;
            float v = 0.0f;
            if (f == 0)       v = x[(size_t)n * TT + t];
            else if (f <= 2)  v = coords[n * 2 + (f - 1)];
            else if (f <= 12) v = env[((size_t)n * NENV + (f - 3)) * TT + t];
            else if (f == 13) v = areas[n];
            else if (f <= 15) v = bird_uv[((size_t)n * 2 + (f - 14)) * TT + t];
            g_featsH[idx] = __float2half_rn(v);
        } else if (idx < S1 + S2) {
            int j = idx - S1;
            int l = j / (NB * HH);
            g_hH[l][0][j - l * NB * HH] = __float2half_rn(0.0f);
        } else {
            int j = idx - S1 - S2;
            int l = j / (NB * HH);
            g_c[l][j - l * NB * HH] = 0.0f;
        }
    }
}

// ---------------------------------------------------------------------------
// Prep 2: weights (sigma-permuted rows, half), biases, folded Wc (k pad 64)
// ---------------------------------------------------------------------------
__global__ void prep_wts(const float* __restrict__ W_in,
                         const float* __restrict__ W_ih,
                         const float* __restrict__ W_hh,
                         const float* __restrict__ b_ih,
                         const float* __restrict__ b_hh) {
    const int T1 = 524288;
    const int T2 = T1 + 262144;
    const int T3 = T2 + 2048;
    const int tot = T3 + FOURH * KPADH;
    for (int i = blockIdx.x * blockDim.x + threadIdx.x; i < tot;
         i += gridDim.x * blockDim.x) {
        if (i < T1) {
            int l = i >> 18;
            int rem = i & 262143;
            int r = rem >> 8;
            int k = rem & 255;
            g_WhhH[l][rem] =
                __float2half_rn(W_hh[l * 262144 + sigma_orig(r) * HH + k]);
        } else if (i < T2) {
            int rem = i - T1;
            int r = rem >> 8;
            int k = rem & 255;
            g_Wih1H[rem] =
                __float2half_rn(W_ih[262144 + sigma_orig(r) * HH + k]);
        } else if (i < T3) {
            int j = i - T2;
            int l = j >> 10;
            int s = j & 1023;
            g_bias[l][s] = b_ih[l * FOURH + s] + b_hh[l * FOURH + s];
        } else {
            int j = i - T3;
            int k = j & 63;
            int r = j >> 6;
            float out = 0.0f;
            if (k < 16) {
                const float* wr = W_ih + sigma_orig(r) * HH;   // layer 0
                float acc = 0.0f;
                #pragma unroll 8
                for (int m = 0; m < HH; m++)
                    acc = fmaf(wr[m], W_in[m * 16 + k], acc);
                out = acc;
            }
            g_WcH[j] = __float2half_rn(out);
        }
    }
}

// ---------------------------------------------------------------------------
// Fused mma.sync fp16 LSTM wavefront step (swizzled smem, BM=64, 3 CTAs/SM)
// ---------------------------------------------------------------------------
__device__ __forceinline__ void issue_tile(const __half* __restrict__ Ab, int as,
                                           const __half* __restrict__ Bb, int bs,
                                           int k0, uint32_t smb, int st,
                                           int rowbase, int gbase, int tid) {
    uint32_t stA = smb + st * STAGE_BYTES;
    uint32_t stB = stA + A_BYTES;
    // A: 64 rows x 8 chunks = 512 cp.async (2 per thread)
    #pragma unroll
    for (int jj = 0; jj < 2; jj++) {
        int idx = tid + jj * 256;
        int row = idx >> 3, ch = idx & 7;
        int chs = ch ^ (row & 7);
        const __half* src = Ab + (size_t)(rowbase + row) * as + k0 + ch * 8;
        uint32_t d = stA + row * ROWB + chs * 16;
        asm volatile("cp.async.cg.shared.global [%0], [%1], 16;"
                     :: "r"(d), "l"(src));
    }
    // B: 128 rows x 8 chunks = 1024 cp.async (4 per thread)
    #pragma unroll
    for (int jj = 0; jj < 4; jj++) {
        int idx = tid + jj * 256;
        int row = idx >> 3, ch = idx & 7;
        int chs = ch ^ (row & 7);
        const __half* src = Bb + (size_t)(gbase + row) * bs + k0 + ch * 8;
        uint32_t d = stB + row * ROWB + chs * 16;
        asm volatile("cp.async.cg.shared.global [%0], [%1], 16;"
                     :: "r"(d), "l"(src));
    }
    asm volatile("cp.async.commit_group;");
}

__device__ __forceinline__ void mma_f16(float* d, const uint32_t* a,
                                        const uint32_t* b) {
    asm volatile(
        "mma.sync.aligned.m16n8k16.row.col.f32.f16.f16.f32 "
        "{%0,%1,%2,%3}, {%4,%5,%6,%7}, {%8,%9}, {%0,%1,%2,%3};"
        : "+f"(d[0]), "+f"(d[1]), "+f"(d[2]), "+f"(d[3])
        : "r"(a[0]), "r"(a[1]), "r"(a[2]), "r"(a[3]), "r"(b[0]), "r"(b[1]));
}

__device__ __forceinline__ void ldm_x4(uint32_t* r, uint32_t addr) {
    asm volatile(
        "ldmatrix.sync.aligned.m8n8.x4.shared.b16 {%0,%1,%2,%3}, [%4];"
        : "=r"(r[0]), "=r"(r[1]), "=r"(r[2]), "=r"(r[3]) : "r"(addr));
}

__global__ __launch_bounds__(256, 3) void lstm_step_mma(int kstep,
                                                        float* __restrict__ out) {
    const int layer = blockIdx.z;
    const int t = (layer == 0) ? kstep : kstep - 1;
    if (t < 0 || t >= TT) return;

    extern __shared__ __align__(16) char dynC[];
    const uint32_t smb = smem_u32(dynC);

    const int tid = threadIdx.x;
    const int wid = tid >> 5;
    const int lane = tid & 31;
    const int gid = lane >> 2;
    const int tig = lane & 3;
    const int wm = (wid & 1) * 32;        // warp row base (2 m-tiles)
    const int wn = (wid >> 1) * 32;       // warp col base (4 n-tiles)
    const int rowbase = blockIdx.x * BM;
    const int gbase = blockIdx.y * BN;
    const int hb = blockIdx.y * 32;

    // ldmatrix lane-invariant components (swizzled layout)
    const int l7 = lane & 7;
    const uint32_t aRow = (uint32_t)(wm + ((lane >> 3) & 1) * 8 + l7) * ROWB;
    const uint32_t bRow = (uint32_t)(wn + ((lane >> 4) & 1) * 8 + l7) * ROWB +
                          A_BYTES;
    const int c0a = (lane >> 4) & 1;
    const int c0b = (lane >> 3) & 1;

    // --- operand selection ---
    const __half *A0, *B0, *A1, *B1;
    int a0s, b0s, K0T;
    if (layer == 0) {
        A0 = g_featsH + (size_t)t * NB * KPADH;  a0s = KPADH;
        B0 = g_WcH;                               b0s = KPADH;
        K0T = 1;
        A1 = g_hH[0][t & 1];
        B1 = g_WhhH[0];
    } else {
        A0 = g_hH[0][(t + 1) & 1];                a0s = HH;
        B0 = g_Wih1H;                             b0s = HH;
        K0T = HH / KT;                            // 4
        A1 = g_hH[1][t & 1];
        B1 = g_WhhH[1];
    }
    const int TK = K0T + HH / KT;                 // layer0: 5, layer1: 8

    float acc[2][4][4];
    #pragma unroll
    for (int i = 0; i < 2; i++)
        #pragma unroll
        for (int j = 0; j < 4; j++)
            #pragma unroll
            for (int k = 0; k < 4; k++) acc[i][j][k] = 0.0f;

    // prologue: stages 0 and 1
    issue_tile(A0, a0s, B0, b0s, 0, smb, 0, rowbase, gbase, tid);
    {
        const __half* Ab = (1 < K0T) ? A0 : A1;
        const __half* Bb = (1 < K0T) ? B0 : B1;
        int as = (1 < K0T) ? a0s : HH;
        int bs = (1 < K0T) ? b0s : HH;
        int k0 = (1 < K0T) ? KT : 0;
        issue_tile(Ab, as, Bb, bs, k0, smb, 1, rowbase, gbase, tid);
    }

    int rd = 0, wr = 2;
    for (int kt = 0; kt < TK; kt++) {
        if (kt == TK - 1) asm volatile("cp.async.wait_group 0;");
        else              asm volatile("cp.async.wait_group 1;");
        __syncthreads();

        if (kt + 2 < TK) {
            int j = kt + 2;
            const __half *Ab, *Bb;
            int as, bs, k0;
            if (j < K0T) { Ab = A0; Bb = B0; as = a0s; bs = b0s; k0 = j * KT; }
            else         { Ab = A1; Bb = B1; as = HH;  bs = HH;  k0 = (j - K0T) * KT; }
            issue_tile(Ab, as, Bb, bs, k0, smb, wr, rowbase, gbase, tid);
        }

        const uint32_t stage = smb + rd * STAGE_BYTES;
        const uint32_t aB = stage + aRow;
        const uint32_t bB = stage + bRow;

        #pragma unroll
        for (int kk = 0; kk < 4; kk++) {
            const uint32_t chA = (uint32_t)(((kk * 2 + c0a) ^ l7) << 4);
            const uint32_t chB = (uint32_t)(((kk * 2 + c0b) ^ l7) << 4);
            uint32_t a[2][4];
            #pragma unroll
            for (int mt = 0; mt < 2; mt++)
                ldm_x4(a[mt], aB + (uint32_t)(mt * 16 * ROWB) + chA);
            uint32_t b[2][4];
            #pragma unroll
            for (int p = 0; p < 2; p++)
                ldm_x4(b[p], bB + (uint32_t)(p * 16 * ROWB) + chB);
            #pragma unroll
            for (int mt = 0; mt < 2; mt++)
                #pragma unroll
                for (int nt = 0; nt < 4; nt++)
                    mma_f16(acc[mt][nt], a[mt], &b[nt >> 1][(nt & 1) * 2]);
        }

        rd++; if (rd == 3) rd = 0;
        wr++; if (wr == 3) wr = 0;
    }
    __syncthreads();   // all stages free -> reuse stage 0 for H/C staging

    // --- LSTM cell epilogue (fp32); old c loaded directly from gmem ---
    float* Hs = (float*)dynC;                       // 64*36*4 = 9216 B
    float* Cw = (float*)(dynC + 9216);              // 9216 B (fits stage0)
    int hq[2];
    float bb[2][4];
    #pragma unroll
    for (int q = 0; q < 2; q++) {
        int hl = ((wid >> 1) * 2 + q) * 4 + tig;
        hq[q] = hl;
        #pragma unroll
        for (int g = 0; g < 4; g++)
            bb[q][g] = g_bias[layer][g * HH + hb + hl];
    }

    const float* cgl = g_c[layer];
    #pragma unroll
    for (int mt = 0; mt < 2; mt++)
        #pragma unroll
        for (int q = 0; q < 2; q++)
            #pragma unroll
            for (int rr = 0; rr < 2; rr++) {
                int row = wm + mt * 16 + gid + rr * 8;
                float co = cgl[(size_t)(rowbase + row) * HH + hb + hq[q]];
                float iv = sigm(acc[mt][2 * q][rr * 2 + 0] + bb[q][0]);
                float fv = sigm(acc[mt][2 * q][rr * 2 + 1] + bb[q][1]);
                float gv = tanh_fast(acc[mt][2 * q + 1][rr * 2 + 0] + bb[q][2]);
                float ov = sigm(acc[mt][2 * q + 1][rr * 2 + 1] + bb[q][3]);
                float cn = fv * co + iv * gv;
                float hn = ov * tanh_fast(cn);
                Cw[row * LDC + hq[q]] = cn;
                Hs[row * LDC + hq[q]] = hn;
            }
    __syncthreads();

    // --- coalesced write-out: half state, fp32 c, fp32 final output ---
    __half* hgH = g_hH[layer][(t + 1) & 1] + (size_t)rowbase * HH + hb;
    float* cg = g_c[layer] + (size_t)rowbase * HH + hb;
    const size_t NH = (size_t)NB * HH;
    float* oh = out + (size_t)layer * NH + (size_t)rowbase * HH + hb;
    float* oc = out + (size_t)(2 + layer) * NH + (size_t)rowbase * HH + hb;
    const bool last = (t == TT - 1);

    #pragma unroll
    for (int j = 0; j < 2; j++) {
        int idx = tid + j * 256;
        int row = idx >> 3, ch = idx & 7;
        float4 hv = *(const float4*)&Hs[row * LDC + ch * 4];
        float4 cv = *(const float4*)&Cw[row * LDC + ch * 4];
        *(float4*)(cg + (size_t)row * HH + ch * 4) = cv;
        __half2 p0 = __floats2half2_rn(hv.x, hv.y);
        __half2 p1 = __floats2half2_rn(hv.z, hv.w);
        __half2* hd = (__half2*)(hgH + (size_t)row * HH + ch * 4);
        hd[0] = p0;
        hd[1] = p1;
        if (last) {
            *(float4*)(oh + (size_t)row * HH + ch * 4) = hv;
            *(float4*)(oc + (size_t)row * HH + ch * 4) = cv;
        }
    }
}

// ---------------------------------------------------------------------------
extern "C" void kernel_launch(void* const* d_in, const int* in_sizes, int n_in,
                              void* d_out, int out_size) {
    const float* x       = (const float*)d_in[0];
    const float* coords  = (const float*)d_in[1];
    const float* env     = (const float*)d_in[2];
    const float* areas   = (const float*)d_in[3];
    const float* bird_uv = (const float*)d_in[4];
    const float* W_in    = (const float*)d_in[5];
    const float* W_ih    = (const float*)d_in[6];
    const float* W_hh    = (const float*)d_in[7];
    const float* b_ih    = (const float*)d_in[8];
    const float* b_hh    = (const float*)d_in[9];
    (void)in_sizes; (void)n_in; (void)out_size;

    cudaFuncSetAttribute(lstm_step_mma,
                         cudaFuncAttributeMaxDynamicSharedMemorySize, SMEM_DYN);

    prep_data<<<8192, 256>>>(x, coords, env, areas, bird_uv);
    prep_wts<<<832, 256>>>(W_in, W_ih, W_hh, b_ih, b_hh);

    dim3 grid(NB / BM, FOURH / BN, 2);   // (128, 8, 2) wavefront over layers
    for (int k = 0; k <= TT; k++)
        lstm_step_mma<<<grid, 256, SMEM_DYN>>>(k, (float*)d_out);
}

// round 14
// speedup vs baseline: 14.1515x; 1.1526x over previous
#include <cuda_runtime.h>
#include <cuda_fp16.h>
#include <cstdint>
#include <math.h>

// Problem constants
#define NB    8192
#define TT    48
#define HH    256
#define NENV  10
#define FOURH 1024
#define KPADH 64            // padded feature K (halfs)

// MMA tile config: CTA 64x128, 8 warps (2x4), warp tile 32x32, m16n8k16 fp16
// KT=64 k per stage, swizzled 128B rows, 3 stages, 1 sync/tile, 3 CTAs/SM.
#define BM    64
#define BN    128
#define KT    64
#define ROWB  128           // bytes per A/B smem row (64 halfs)
#define A_BYTES     (BM * ROWB)              // 8192
#define B_BYTES     (BN * ROWB)              // 16384
#define STAGE_BYTES (A_BYTES + B_BYTES)      // 24576
#define LDC   36            // float stride for H/C staging
#define SMEM_DYN (3 * STAGE_BYTES)           // 73728 B

// ---------------------------------------------------------------------------
// Scratch
// ---------------------------------------------------------------------------
__device__ __align__(256) __half g_hH[2][2][NB * HH];   // [layer][pp][n][h]
__device__ __align__(256) float  g_c[2][NB * HH];       // [layer][n][h] fp32
__device__ __align__(256) __half g_featsH[TT * NB * KPADH];
__device__ __align__(256) __half g_WhhH[2][FOURH * HH]; // [r_perm][k]
__device__ __align__(256) __half g_Wih1H[FOURH * HH];
__device__ __align__(256) __half g_WcH[FOURH * KPADH];  // folded W_ih0 @ W_in
__device__ __align__(256) float  g_bias[2][FOURH];      // original layout g*256+h

__device__ __forceinline__ float sigm(float v) {
    return 1.0f / (1.0f + __expf(-v));
}
__device__ __forceinline__ float tanh_fast(float v) {
    return 2.0f / (1.0f + __expf(-2.0f * v)) - 1.0f;
}
__device__ __forceinline__ uint32_t smem_u32(const void* p) {
    return (uint32_t)__cvta_generic_to_shared(p);
}

// Column permutation sigma: permuted gate-row r -> original row (gate*256 + h)
__device__ __forceinline__ int sigma_orig(int r) {
    int blk = r >> 7;
    int c = r & 127;
    int h = blk * 32 + ((c >> 4) << 2) + ((c >> 1) & 3);
    int gate = (((c >> 3) & 1) << 1) | (c & 1);
    return gate * HH + h;
}

// ---------------------------------------------------------------------------
// Prep 1: feats -> half [t][n][64] (pad 0), zero h (slot 0) and c
// ---------------------------------------------------------------------------
__global__ void prep_data(const float* __restrict__ x,
                          const float* __restrict__ coords,
                          const float* __restrict__ env,
                          const float* __restrict__ areas,
                          const float* __restrict__ bird_uv) {
    const int S1 = TT * NB * KPADH;
    const int S2 = 2 * NB * HH;
    const int tot = S1 + S2 + S2;
    for (int idx = blockIdx.x * blockDim.x + threadIdx.x; idx < tot;
         idx += gridDim.x * blockDim.x) {
        if (idx < S1) {
            int f = idx & 63;
            int n = (idx >> 6) & (NB - 1);
            int t = idx >> 19;
            float v = 0.0f;
            if (f == 0)       v = x[(size_t)n * TT + t];
            else if (f <= 2)  v = coords[n * 2 + (f - 1)];
            else if (f <= 12) v = env[((size_t)n * NENV + (f - 3)) * TT + t];
            else if (f == 13) v = areas[n];
            else if (f <= 15) v = bird_uv[((size_t)n * 2 + (f - 14)) * TT + t];
            g_featsH[idx] = __float2half_rn(v);
        } else if (idx < S1 + S2) {
            int j = idx - S1;
            int l = j / (NB * HH);
            g_hH[l][0][j - l * NB * HH] = __float2half_rn(0.0f);
        } else {
            int j = idx - S1 - S2;
            int l = j / (NB * HH);
            g_c[l][j - l * NB * HH] = 0.0f;
        }
    }
}

// ---------------------------------------------------------------------------
// Prep 2: weights (sigma-permuted rows, half), biases, folded Wc (k pad 64)
// ---------------------------------------------------------------------------
__global__ void prep_wts(const float* __restrict__ W_in,
                         const float* __restrict__ W_ih,
                         const float* __restrict__ W_hh,
                         const float* __restrict__ b_ih,
                         const float* __restrict__ b_hh) {
    const int T1 = 524288;
    const int T2 = T1 + 262144;
    const int T3 = T2 + 2048;
    const int tot = T3 + FOURH * KPADH;
    for (int i = blockIdx.x * blockDim.x + threadIdx.x; i < tot;
         i += gridDim.x * blockDim.x) {
        if (i < T1) {
            int l = i >> 18;
            int rem = i & 262143;
            int r = rem >> 8;
            int k = rem & 255;
            g_WhhH[l][rem] =
                __float2half_rn(W_hh[l * 262144 + sigma_orig(r) * HH + k]);
        } else if (i < T2) {
            int rem = i - T1;
            int r = rem >> 8;
            int k = rem & 255;
            g_Wih1H[rem] =
                __float2half_rn(W_ih[262144 + sigma_orig(r) * HH + k]);
        } else if (i < T3) {
            int j = i - T2;
            int l = j >> 10;
            int s = j & 1023;
            g_bias[l][s] = b_ih[l * FOURH + s] + b_hh[l * FOURH + s];
        } else {
            int j = i - T3;
            int k = j & 63;
            int r = j >> 6;
            float out = 0.0f;
            if (k < 16) {
                const float* wr = W_ih + sigma_orig(r) * HH;   // layer 0
                float acc = 0.0f;
                #pragma unroll 8
                for (int m = 0; m < HH; m++)
                    acc = fmaf(wr[m], W_in[m * 16 + k], acc);
                out = acc;
            }
            g_WcH[j] = __float2half_rn(out);
        }
    }
}

// ---------------------------------------------------------------------------
// Fused mma.sync fp16 LSTM wavefront step — templated body, fully unrolled
// ---------------------------------------------------------------------------
__device__ __forceinline__ void issue_tile(const __half* __restrict__ Ab, int as,
                                           const __half* __restrict__ Bb, int bs,
                                           int k0, uint32_t smb, int st,
                                           int rowbase, int gbase, int tid) {
    uint32_t stA = smb + st * STAGE_BYTES;
    uint32_t stB = stA + A_BYTES;
    #pragma unroll
    for (int jj = 0; jj < 2; jj++) {
        int idx = tid + jj * 256;
        int row = idx >> 3, ch = idx & 7;
        int chs = ch ^ (row & 7);
        const __half* src = Ab + (size_t)(rowbase + row) * as + k0 + ch * 8;
        uint32_t d = stA + row * ROWB + chs * 16;
        asm volatile("cp.async.cg.shared.global [%0], [%1], 16;"
                     :: "r"(d), "l"(src));
    }
    #pragma unroll
    for (int jj = 0; jj < 4; jj++) {
        int idx = tid + jj * 256;
        int row = idx >> 3, ch = idx & 7;
        int chs = ch ^ (row & 7);
        const __half* src = Bb + (size_t)(gbase + row) * bs + k0 + ch * 8;
        uint32_t d = stB + row * ROWB + chs * 16;
        asm volatile("cp.async.cg.shared.global [%0], [%1], 16;"
                     :: "r"(d), "l"(src));
    }
    asm volatile("cp.async.commit_group;");
}

__device__ __forceinline__ void mma_f16(float* d, const uint32_t* a,
                                        const uint32_t* b) {
    asm volatile(
        "mma.sync.aligned.m16n8k16.row.col.f32.f16.f16.f32 "
        "{%0,%1,%2,%3}, {%4,%5,%6,%7}, {%8,%9}, {%0,%1,%2,%3};"
        : "+f"(d[0]), "+f"(d[1]), "+f"(d[2]), "+f"(d[3])
        : "r"(a[0]), "r"(a[1]), "r"(a[2]), "r"(a[3]), "r"(b[0]), "r"(b[1]));
}

__device__ __forceinline__ void ldm_x4(uint32_t* r, uint32_t addr) {
    asm volatile(
        "ldmatrix.sync.aligned.m8n8.x4.shared.b16 {%0,%1,%2,%3}, [%4];"
        : "=r"(r[0]), "=r"(r[1]), "=r"(r[2]), "=r"(r[3]) : "r"(addr));
}

template <int LAYER>
__device__ __forceinline__ void lstm_body(int t, char* dynC,
                                          float* __restrict__ out) {
    const uint32_t smb = smem_u32(dynC);
    const int tid = threadIdx.x;
    const int wid = tid >> 5;
    const int lane = tid & 31;
    const int gid = lane >> 2;
    const int tig = lane & 3;
    const int wm = (wid & 1) * 32;
    const int wn = (wid >> 1) * 32;
    const int rowbase = blockIdx.x * BM;
    const int gbase = blockIdx.y * BN;
    const int hb = blockIdx.y * 32;

    const int l7 = lane & 7;
    const uint32_t aRow = (uint32_t)(wm + ((lane >> 3) & 1) * 8 + l7) * ROWB;
    const uint32_t bRow = (uint32_t)(wn + ((lane >> 4) & 1) * 8 + l7) * ROWB +
                          A_BYTES;
    const int c0a = (lane >> 4) & 1;
    const int c0b = (lane >> 3) & 1;

    // --- compile-time operand config ---
    constexpr int K0T = (LAYER == 0) ? 1 : 4;
    constexpr int TK = K0T + HH / KT;             // 5 or 8
    constexpr int A0S = (LAYER == 0) ? KPADH : HH;
    constexpr int B0S = (LAYER == 0) ? KPADH : HH;

    const __half* A0 = (LAYER == 0)
        ? g_featsH + (size_t)t * NB * KPADH
        : g_hH[0][(t + 1) & 1];
    const __half* B0 = (LAYER == 0) ? g_WcH : g_Wih1H;
    const __half* A1 = g_hH[LAYER][t & 1];
    const __half* B1 = g_WhhH[LAYER];

    float acc[2][4][4];
    #pragma unroll
    for (int i = 0; i < 2; i++)
        #pragma unroll
        for (int j = 0; j < 4; j++)
            #pragma unroll
            for (int k = 0; k < 4; k++) acc[i][j][k] = 0.0f;

    // prologue: stages 0 and 1 (all selection compile-time)
    issue_tile(A0, A0S, B0, B0S, 0, smb, 0, rowbase, gbase, tid);
    if (1 < K0T)
        issue_tile(A0, A0S, B0, B0S, KT, smb, 1, rowbase, gbase, tid);
    else
        issue_tile(A1, HH, B1, HH, 0, smb, 1, rowbase, gbase, tid);

    #pragma unroll
    for (int kt = 0; kt < TK; kt++) {
        if (kt == TK - 1) asm volatile("cp.async.wait_group 0;");
        else              asm volatile("cp.async.wait_group 1;");
        __syncthreads();

        if (kt + 2 < TK) {
            constexpr_issue:
            {
                const int j = kt + 2;
                if (j < K0T)
                    issue_tile(A0, A0S, B0, B0S, j * KT, smb, (kt + 2) % 3,
                               rowbase, gbase, tid);
                else
                    issue_tile(A1, HH, B1, HH, (j - K0T) * KT, smb,
                               (kt + 2) % 3, rowbase, gbase, tid);
            }
        }

        const uint32_t stage = smb + (kt % 3) * STAGE_BYTES;
        const uint32_t aB = stage + aRow;
        const uint32_t bB = stage + bRow;

        #pragma unroll
        for (int kk = 0; kk < 4; kk++) {
            const uint32_t chA = (uint32_t)(((kk * 2 + c0a) ^ l7) << 4);
            const uint32_t chB = (uint32_t)(((kk * 2 + c0b) ^ l7) << 4);
            uint32_t a[2][4];
            #pragma unroll
            for (int mt = 0; mt < 2; mt++)
                ldm_x4(a[mt], aB + (uint32_t)(mt * 16 * ROWB) + chA);
            uint32_t b[2][4];
            #pragma unroll
            for (int p = 0; p < 2; p++)
                ldm_x4(b[p], bB + (uint32_t)(p * 16 * ROWB) + chB);
            #pragma unroll
            for (int mt = 0; mt < 2; mt++)
                #pragma unroll
                for (int nt = 0; nt < 4; nt++)
                    mma_f16(acc[mt][nt], a[mt], &b[nt >> 1][(nt & 1) * 2]);
        }
    }
    __syncthreads();   // all stages free -> reuse stage 0 for H/C staging

    // --- LSTM cell epilogue (fp32); old c loaded directly from gmem ---
    float* Hs = (float*)dynC;                       // 64*36*4 = 9216 B
    float* Cw = (float*)(dynC + 9216);              // 9216 B (fits stage0)
    int hq[2];
    float bb[2][4];
    #pragma unroll
    for (int q = 0; q < 2; q++) {
        int hl = ((wid >> 1) * 2 + q) * 4 + tig;
        hq[q] = hl;
        #pragma unroll
        for (int g = 0; g < 4; g++)
            bb[q][g] = g_bias[LAYER][g * HH + hb + hl];
    }

    const float* cgl = g_c[LAYER];
    #pragma unroll
    for (int mt = 0; mt < 2; mt++)
        #pragma unroll
        for (int q = 0; q < 2; q++)
            #pragma unroll
            for (int rr = 0; rr < 2; rr++) {
                int row = wm + mt * 16 + gid + rr * 8;
                float co = cgl[(size_t)(rowbase + row) * HH + hb + hq[q]];
                float iv = sigm(acc[mt][2 * q][rr * 2 + 0] + bb[q][0]);
                float fv = sigm(acc[mt][2 * q][rr * 2 + 1] + bb[q][1]);
                float gv = tanh_fast(acc[mt][2 * q + 1][rr * 2 + 0] + bb[q][2]);
                float ov = sigm(acc[mt][2 * q + 1][rr * 2 + 1] + bb[q][3]);
                float cn = fv * co + iv * gv;
                float hn = ov * tanh_fast(cn);
                Cw[row * LDC + hq[q]] = cn;
                Hs[row * LDC + hq[q]] = hn;
            }
    __syncthreads();

    // --- coalesced write-out: half state, fp32 c, fp32 final output ---
    __half* hgH = g_hH[LAYER][(t + 1) & 1] + (size_t)rowbase * HH + hb;
    float* cg = g_c[LAYER] + (size_t)rowbase * HH + hb;
    const size_t NH = (size_t)NB * HH;
    float* oh = out + (size_t)LAYER * NH + (size_t)rowbase * HH + hb;
    float* oc = out + (size_t)(2 + LAYER) * NH + (size_t)rowbase * HH + hb;
    const bool last = (t == TT - 1);

    #pragma unroll
    for (int j = 0; j < 2; j++) {
        int idx = tid + j * 256;
        int row = idx >> 3, ch = idx & 7;
        float4 hv = *(const float4*)&Hs[row * LDC + ch * 4];
        float4 cv = *(const float4*)&Cw[row * LDC + ch * 4];
        *(float4*)(cg + (size_t)row * HH + ch * 4) = cv;
        __half2 p0 = __floats2half2_rn(hv.x, hv.y);
        __half2 p1 = __floats2half2_rn(hv.z, hv.w);
        __half2* hd = (__half2*)(hgH + (size_t)row * HH + ch * 4);
        hd[0] = p0;
        hd[1] = p1;
        if (last) {
            *(float4*)(oh + (size_t)row * HH + ch * 4) = hv;
            *(float4*)(oc + (size_t)row * HH + ch * 4) = cv;
        }
    }
}

__global__ __launch_bounds__(256, 3) void lstm_step_mma(int kstep,
                                                        float* __restrict__ out) {
    const int layer = blockIdx.z;
    const int t = (layer == 0) ? kstep : kstep - 1;
    if (t < 0 || t >= TT) return;

    extern __shared__ __align__(16) char dynC[];
    if (layer == 0) lstm_body<0>(t, dynC, out);
    else            lstm_body<1>(t, dynC, out);
}

// ---------------------------------------------------------------------------
extern "C" void kernel_launch(void* const* d_in, const int* in_sizes, int n_in,
                              void* d_out, int out_size) {
    const float* x       = (const float*)d_in[0];
    const float* coords  = (const float*)d_in[1];
    const float* env     = (const float*)d_in[2];
    const float* areas   = (const float*)d_in[3];
    const float* bird_uv = (const float*)d_in[4];
    const float* W_in    = (const float*)d_in[5];
    const float* W_ih    = (const float*)d_in[6];
    const float* W_hh    = (const float*)d_in[7];
    const float* b_ih    = (const float*)d_in[8];
    const float* b_hh    = (const float*)d_in[9];
    (void)in_sizes; (void)n_in; (void)out_size;

    cudaFuncSetAttribute(lstm_step_mma,
                         cudaFuncAttributeMaxDynamicSharedMemorySize, SMEM_DYN);

    prep_data<<<8192, 256>>>(x, coords, env, areas, bird_uv);
    prep_wts<<<832, 256>>>(W_in, W_ih, W_hh, b_ih, b_hh);

    dim3 grid(NB / BM, FOURH / BN, 2);   // (128, 8, 2) wavefront over layers
    for (int k = 0; k <= TT; k++)
        lstm_step_mma<<<grid, 256, SMEM_DYN>>>(k, (float*)d_out);
}